// round 13
// baseline (speedup 1.0000x reference)
#include <cuda_runtime.h>
#include <cuda_bf16.h>
#include <math.h>
#include <stdint.h>

#ifndef M_PI
#define M_PI 3.14159265358979323846
#endif

#define FULLMASK 0xffffffffu

// ---------------- scratch (static device globals; no allocations) ----------------
__device__ float2   g_F[16777216];    // packed spectrum Z = fft2(x1 + i x2), shifted  [1024 pairs][16384]
__device__ float2   g_G[16777216];    // boundary frame of W (1743 px per pair; interior unused)
__device__ uint32_t g_Rhi[16777216];  // real(ifft2) bf16 hi, packed channel pairs [B*128][16384]
__device__ uint32_t g_Rlo[16777216];  // residual bf16 lo
__device__ float    g_kern[8 * 49];   // per-batch 7x7 kernel
__device__ uint32_t g_Whi[32768];     // refine_w split: [c2=128][o=256]
__device__ uint32_t g_Wlo[32768];     // residuals

// ---------------- complex helpers ----------------
__device__ __forceinline__ float2 cadd(float2 a, float2 b) { return make_float2(a.x + b.x, a.y + b.y); }
__device__ __forceinline__ float2 csub(float2 a, float2 b) { return make_float2(a.x - b.x, a.y - b.y); }
__device__ __forceinline__ float2 cmul(float2 a, float2 b) {
  return make_float2(a.x * b.x - a.y * b.y, a.x * b.y + a.y * b.x);
}

// ---------------- bf16 split helpers ----------------
__device__ __forceinline__ void split2_bf16(float xe, float xo, uint32_t& hi, uint32_t& lo) {
  __nv_bfloat16 he = __float2bfloat16_rn(xe);
  __nv_bfloat16 ho = __float2bfloat16_rn(xo);
  float re = xe - __bfloat162float(he);
  float ro = xo - __bfloat162float(ho);
  __nv_bfloat16 le = __float2bfloat16_rn(re);
  __nv_bfloat16 lo16 = __float2bfloat16_rn(ro);
  hi = (uint32_t)__bfloat16_as_ushort(he) | ((uint32_t)__bfloat16_as_ushort(ho) << 16);
  lo = (uint32_t)__bfloat16_as_ushort(le) | ((uint32_t)__bfloat16_as_ushort(lo16) << 16);
}

// ---------------- warp-resident 128-pt DIF FFT ----------------
template<int SGN>
__device__ __forceinline__ void make_twiddles(int lane, float2 tw[7]) {
  const float TP = 6.283185307179586f * (float)SGN;
  float fr[7] = { lane / 128.f, (lane + 32) / 128.f, lane / 64.f,
                  (lane & 15) / 32.f, (lane & 7) / 16.f, (lane & 3) / 8.f, (lane & 1) / 4.f };
#pragma unroll
  for (int i = 0; i < 7; i++) {
    float s, c;
    sincosf(TP * fr[i], &s, &c);
    tw[i] = make_float2(c, s);
  }
}

__device__ __forceinline__ void fft128(float2 v[4], const float2 tw[7], int lane) {
  float2 t, u;
  t = v[0]; u = v[2]; v[0] = cadd(t, u); v[2] = cmul(csub(t, u), tw[0]);
  t = v[1]; u = v[3]; v[1] = cadd(t, u); v[3] = cmul(csub(t, u), tw[1]);
  t = v[0]; u = v[1]; v[0] = cadd(t, u); v[1] = cmul(csub(t, u), tw[2]);
  t = v[2]; u = v[3]; v[2] = cadd(t, u); v[3] = cmul(csub(t, u), tw[2]);
#pragma unroll
  for (int hi = 0; hi < 5; hi++) {
    int h = 16 >> hi;
    bool up = (lane & h) != 0;
#pragma unroll
    for (int s = 0; s < 4; s++) {
      float prx = __shfl_xor_sync(FULLMASK, v[s].x, h);
      float pry = __shfl_xor_sync(FULLMASK, v[s].y, h);
      float2 pr = make_float2(prx, pry);
      if (hi < 4) {
        v[s] = up ? cmul(csub(pr, v[s]), tw[3 + hi]) : cadd(v[s], pr);
      } else {
        v[s] = up ? csub(pr, v[s]) : cadd(v[s], pr);
      }
    }
  }
}

__device__ __forceinline__ int bitrev7(int p) { return (int)(__brev((unsigned)p) >> 25); }

// ---------------- forward FFT (channel-pair packed): x_low -> g_F (packed Z) ----------------
__global__ void __launch_bounds__(1024) fwd_fft_pair_kernel(const float* __restrict__ x) {
  extern __shared__ float sm[];
  float* sre = sm;
  float* sim = sm + 128 * 129;
  int pair = blockIdx.x;
  int ch1 = pair * 2, ch2 = ch1 + 1;
  int tid = threadIdx.x;
  int warp = tid >> 5, lane = tid & 31;
  float2 tw[7];
  make_twiddles<-1>(lane, tw);
  const float* x1 = x + (size_t)ch1 * 16384;
  const float* x2 = x + (size_t)ch2 * 16384;

  for (int r = warp; r < 128; r += 32) {
    float2 v[4];
#pragma unroll
    for (int s = 0; s < 4; s++) {
      int c = s * 32 + lane;
      v[s] = make_float2(x1[r * 128 + c] * 0.0078125f, x2[r * 128 + c] * 0.0078125f);
    }
    fft128(v, tw, lane);
#pragma unroll
    for (int s = 0; s < 4; s++) {
      int p = s * 32 + lane;
      int n = bitrev7(p) ^ 64;
      sre[r * 129 + n] = v[s].x;
      sim[r * 129 + n] = v[s].y;
    }
  }
  __syncthreads();
  for (int c = warp; c < 128; c += 32) {
    float2 v[4];
#pragma unroll
    for (int s = 0; s < 4; s++) {
      int p = s * 32 + lane;
      v[s] = make_float2(sre[p * 129 + c], sim[p * 129 + c]);
    }
    fft128(v, tw, lane);
#pragma unroll
    for (int s = 0; s < 4; s++) {
      int p = s * 32 + lane;
      int n = bitrev7(p) ^ 64;
      sre[n * 129 + c] = v[s].x;
      sim[n * 129 + c] = v[s].y;
    }
  }
  __syncthreads();
  float2* Zb = g_F + (size_t)pair * 16384;
  for (int i = tid; i < 16384; i += 1024) {
    int r = i >> 7, c = i & 127;
    Zb[i] = make_float2(sre[r * 129 + c], sim[r * 129 + c]);
  }
}

// ---------------- tiny path: center magnitudes (unpacked from Z) -> MLP -> kernel ----------------
__global__ void __launch_bounds__(256) mlp_kernel(const float* __restrict__ w1, const float* __restrict__ b1,
                                                  const float* __restrict__ w2, const float* __restrict__ b2) {
  int b = blockIdx.x;
  int t = threadIdx.x;
  __shared__ float part[49][4];
  __shared__ float flat[49];
  __shared__ float hbuf[32];
  __shared__ float prm[3];
  __shared__ float kv[49];
  __shared__ float ksum;

  if (t < 196) {
    int p = t >> 2, q = t & 3;
    int i = p / 7, j = p % 7;
    int im = 6 - i, jm = 6 - j;
    const float2* Zb = g_F + ((size_t)(b * 128 + q * 32)) * 16384;
    float s = 0.f;
#pragma unroll 4
    for (int pr = 0; pr < 32; pr++) {
      const float2* Zp = Zb + (size_t)pr * 16384;
      float2 z = Zp[(61 + i) * 128 + (61 + j)];
      float2 zm = Zp[(61 + im) * 128 + (61 + jm)];
      float e1 = z.x + zm.x, e2 = z.y - zm.y;
      float o1 = z.x - zm.x, o2 = z.y + zm.y;
      s += 0.5f * (sqrtf(e1 * e1 + e2 * e2) + sqrtf(o1 * o1 + o2 * o2));
    }
    part[p][q] = s;
  }
  __syncthreads();
  if (t < 49) flat[t] = (part[t][0] + part[t][1] + part[t][2] + part[t][3]) * (1.f / 256.f);
  __syncthreads();
  if (t < 32) {
    float a = b1[t];
#pragma unroll
    for (int i = 0; i < 49; i++) a += flat[i] * w1[t * 49 + i];
    hbuf[t] = fmaxf(a, 0.f);
  }
  __syncthreads();
  if (t < 3) {
    float a = b2[t];
#pragma unroll
    for (int u = 0; u < 32; u++) a += hbuf[u] * w2[t * 32 + u];
    prm[t] = a;
  }
  __syncthreads();
  if (t < 49) {
    float theta = atan2f(prm[0], prm[1]) * 0.5f + (float)M_PI * 0.5f;
    float lam1 = expf(prm[2]);
    float lam2 = 1.f / (lam1 + 1e-8f);
    float ct = cosf(theta), st = sinf(theta);
    int i = t / 7, j = t % 7;
    float yy = (float)(i - 3), xx = (float)(j - 3);
    float xr = xx * ct + yy * st;
    float yr = -xx * st + yy * ct;
    kv[t] = expf(-(xr * xr / (2.f * lam1 * lam1) + yr * yr / (2.f * lam2 * lam2)));
  }
  __syncthreads();
  if (t == 0) {
    float s = 0.f;
    for (int i = 0; i < 49; i++) s += kv[i];
    ksum = s;
  }
  __syncthreads();
  if (t < 49) g_kern[b * 49 + t] = kv[t] / (ksum + 1e-8f);
}

// ---------------- boundary frame: exact pad/mirror weights -> g_G frame (1743 px/pair) ----------------
// W(n) = sum_D k(D) * Z((n+D) mod 128) * 0.5*(a1*a2 + b1*b2)
__global__ void __launch_bounds__(256) bconv_kernel() {
  __shared__ float kc[49];
  int pair = blockIdx.x;
  int b = pair >> 7;
  int tid = threadIdx.x;
  if (tid < 49) kc[tid] = g_kern[b * 49 + tid];
  __syncthreads();
  const float2* Zb = g_F + (size_t)pair * 16384;
  float2* Wb = g_G + (size_t)pair * 16384;
  for (int idx = tid; idx < 1743; idx += 256) {
    int n1, n2;
    if (idx < 896) {
      int r = idx >> 7;
      n1 = (r < 4) ? r : (121 + r);
      n2 = idx & 127;
    } else {
      int j = idx - 896;
      n1 = 4 + j / 7;
      int c = j % 7;
      n2 = (c < 4) ? c : (121 + c);
    }
    float wy[7], wz[7], vy[7], vz[7];
#pragma unroll
    for (int d = 0; d < 7; d++) {
      int dd = d - 3;
      int j1 = n1 + dd, j2 = n2 + dd;
      wy[d] = (j1 >= 0 && j1 <= 127) ? 1.f : 0.f;
      vy[d] = ((n1 >= 1) ? (j1 >= 1 && j1 <= 128) : (dd <= 0)) ? 1.f : 0.f;
      wz[d] = (j2 >= 0 && j2 <= 127) ? 1.f : 0.f;
      vz[d] = ((n2 >= 1) ? (j2 >= 1 && j2 <= 128) : (dd <= 0)) ? 1.f : 0.f;
    }
    float sre = 0.f, simv = 0.f;
#pragma unroll
    for (int dy = 0; dy < 7; dy++) {
      int r = (n1 + dy - 3) & 127;
      const float2* Zr = Zb + r * 128;
#pragma unroll
      for (int dx = 0; dx < 7; dx++) {
        float wt = 0.5f * (wy[dy] * wz[dx] + vy[dy] * vz[dx]) * kc[dy * 7 + dx];
        float2 in = Zr[(n2 + dx - 3) & 127];
        sre += in.x * wt;
        simv += in.y * wt;
      }
    }
    Wb[n1 * 128 + n2] = make_float2(sre, simv);
  }
}

// ---------------- fused: interior circular conv (from Z strips) + frame (from g_G) + 2D IFFT + bf16 split ----------------
// smem: workspace sre/sim (128*129 each) + strip [38][134] float2 (halo-padded, circular)
__global__ void __launch_bounds__(1024) inv_fused_kernel() {
  extern __shared__ float sm[];
  float* sre = sm;
  float* sim = sm + 128 * 129;
  float2* strip = (float2*)(sm + 2 * 128 * 129);   // [38][134]
  __shared__ float kc[49];
  int pair = blockIdx.x;
  int bb = pair >> 7;
  int tid = threadIdx.x;
  int warp = tid >> 5, lane = tid & 31;
  if (tid < 49) kc[tid] = g_kern[bb * 49 + tid];
  float2 tw[7];
  make_twiddles<1>(lane, tw);
  const float2* Zb = g_F + (size_t)pair * 16384;
  const float2* Gb = g_G + (size_t)pair * 16384;

  const float SC = 0.0078125f;
  for (int t = 0; t < 4; t++) {
    __syncthreads();   // strip reuse guard (also orders kc on first pass)
    int base = t * 32 - 3;
    for (int i = tid; i < 38 * 134; i += 1024) {
      int sr = i / 134, sc = i % 134;
      strip[sr * 134 + sc] = Zb[((base + sr) & 127) * 128 + ((sc - 3) & 127)];
    }
    __syncthreads();
    int r = t * 32 + warp;
    bool rowB = (r <= 3 || r >= 125);
    float2 v[4];
#pragma unroll
    for (int s = 0; s < 4; s++) {
      int c0 = (s * 32 + lane) ^ 64;   // ifftshifted column position
      if (rowB || c0 <= 3 || c0 >= 125) {
        float2 g = Gb[r * 128 + c0];   // exact frame value from bconv
        v[s] = make_float2(g.x * SC, g.y * SC);
      } else {
        float ar = 0.f, ai = 0.f;
#pragma unroll
        for (int dy = 0; dy < 7; dy++) {
          const float2* row = strip + (warp + dy) * 134 + c0;   // strip col c0+dx == physical c0+dx-3
#pragma unroll
          for (int dx = 0; dx < 7; dx++) {
            float2 in = row[dx];
            float k = kc[dy * 7 + dx];
            ar += in.x * k;
            ai += in.y * k;
          }
        }
        v[s] = make_float2(ar * SC, ai * SC);
      }
    }
    fft128(v, tw, lane);
#pragma unroll
    for (int s = 0; s < 4; s++) {
      int p = s * 32 + lane;
      int n = bitrev7(p);
      sre[r * 129 + n] = v[s].x;
      sim[r * 129 + n] = v[s].y;
    }
  }
  __syncthreads();
  for (int c = warp; c < 128; c += 32) {
    float2 v[4];
#pragma unroll
    for (int s = 0; s < 4; s++) {
      int ridx = (s * 32 + lane) ^ 64;      // ifftshift on rows
      v[s] = make_float2(sre[ridx * 129 + c], sim[ridx * 129 + c]);
    }
    fft128(v, tw, lane);
#pragma unroll
    for (int s = 0; s < 4; s++) {
      int p = s * 32 + lane;
      int n = bitrev7(p);
      sre[n * 129 + c] = v[s].x;
      sim[n * 129 + c] = v[s].y;
    }
  }
  __syncthreads();
  uint32_t* Rh = g_Rhi + (size_t)pair * 16384;
  uint32_t* Rl = g_Rlo + (size_t)pair * 16384;
  for (int i = tid; i < 16384; i += 1024) {
    int r = i >> 7, c = i & 127;
    uint32_t hi, lo;
    split2_bf16(sre[r * 129 + c], sim[r * 129 + c], hi, lo);
    Rh[i] = hi;
    Rl[i] = lo;
  }
}

// ---------------- weight prep: refine_w -> bf16-split packed channel pairs ----------------
__global__ void __launch_bounds__(256) wsplit_kernel(const float* __restrict__ W) {
  int idx = blockIdx.x * 256 + threadIdx.x;
  int c2 = idx & 127, o = idx >> 7;
  float xe = W[o * 256 + 2 * c2];
  float xo = W[o * 256 + 2 * c2 + 1];
  uint32_t hi, lo;
  split2_bf16(xe, xo, hi, lo);
  g_Whi[c2 * 256 + o] = hi;
  g_Wlo[c2 * 256 + o] = lo;
}

// ---------------- bf16 MMA helper ----------------
__device__ __forceinline__ void mma_bf16(float* c, uint32_t a0, uint32_t a1, uint32_t a2, uint32_t a3,
                                         uint32_t b0, uint32_t b1) {
  asm volatile(
      "mma.sync.aligned.m16n8k16.row.col.f32.bf16.bf16.f32 "
      "{%0,%1,%2,%3}, {%4,%5,%6,%7}, {%8,%9}, {%0,%1,%2,%3};"
      : "+f"(c[0]), "+f"(c[1]), "+f"(c[2]), "+f"(c[3])
      : "r"(a0), "r"(a1), "r"(a2), "r"(a3), "r"(b0), "r"(b1));
}

// ---------------- channel mix GEMM (3-term bf16) + bilinear epilogue ----------------
// Block: 8 warps cover FULL o=256 (warp tile 32o x 64w); block w-tile 64 (grid y = w half).
// Removes the duplicated Rhi/Rlo reads of the previous 128-o split.
__global__ void __launch_bounds__(256, 2) mix_kernel(const float* __restrict__ xh, float* __restrict__ out) {
  int b = blockIdx.z;
  int h = blockIdx.x;
  int wBase = blockIdx.y * 64;
  int tid = threadIdx.x;
  int warp = tid >> 5, lane = tid & 31;
  int lr = lane >> 2, lc = lane & 3;
  int warpO = warp * 32;

  __shared__ uint2 As[16][264];   // [k2][o 0..255]  {hi,lo}
  __shared__ uint2 Bs[16][72];    // [k2][w 0..63]

  float acc[2][8][4];
#pragma unroll
  for (int mt = 0; mt < 2; mt++)
#pragma unroll
    for (int nt = 0; nt < 8; nt++)
#pragma unroll
      for (int q = 0; q < 4; q++) acc[mt][nt][q] = 0.f;

  const uint32_t* RhB = g_Rhi + (size_t)b * 128 * 16384 + h * 128 + wBase;
  const uint32_t* RlB = g_Rlo + (size_t)b * 128 * 16384 + h * 128 + wBase;

  for (int kb = 0; kb < 8; kb++) {
    __syncthreads();
#pragma unroll
    for (int it = 0; it < 8; it++) {        // A: 16 k2 x 128 o2 = 2048 items
      int item = it * 256 + tid;
      int o2 = item & 127;
      int k2 = item >> 7;
      uint2 ah = *(const uint2*)&g_Whi[(kb * 16 + k2) * 256 + o2 * 2];
      uint2 al = *(const uint2*)&g_Wlo[(kb * 16 + k2) * 256 + o2 * 2];
      *(uint4*)&As[k2][o2 * 2] = make_uint4(ah.x, al.x, ah.y, al.y);
    }
#pragma unroll
    for (int it = 0; it < 2; it++) {        // B: 16 k2 x 32 w2 = 512 items
      int item = it * 256 + tid;
      int w2 = item & 31;
      int k2 = item >> 5;
      uint2 bh = *(const uint2*)&RhB[(size_t)(kb * 16 + k2) * 16384 + w2 * 2];
      uint2 bl = *(const uint2*)&RlB[(size_t)(kb * 16 + k2) * 16384 + w2 * 2];
      *(uint4*)&Bs[k2][w2 * 2] = make_uint4(bh.x, bl.x, bh.y, bl.y);
    }
    __syncthreads();
#pragma unroll
    for (int s = 0; s < 2; s++) {
      uint2 af[2][4];
#pragma unroll
      for (int mt = 0; mt < 2; mt++) {
#pragma unroll
        for (int rg = 0; rg < 4; rg++) {
          int k2 = s * 8 + lc + 4 * (rg >> 1);
          int o = warpO + mt * 16 + lr + 8 * (rg & 1);
          af[mt][rg] = As[k2][o];
        }
      }
      const uint2* bRow0 = &Bs[s * 8 + lc][lr];
      const uint2* bRow1 = &Bs[s * 8 + lc + 4][lr];
#pragma unroll
      for (int nt = 0; nt < 8; nt++) {
        uint2 b0 = bRow0[nt * 8];
        uint2 b1 = bRow1[nt * 8];
#pragma unroll
        for (int mt = 0; mt < 2; mt++) {
          mma_bf16(acc[mt][nt], af[mt][0].x, af[mt][1].x, af[mt][2].x, af[mt][3].x, b0.x, b1.x);
          mma_bf16(acc[mt][nt], af[mt][0].x, af[mt][1].x, af[mt][2].x, af[mt][3].x, b0.y, b1.y);
          mma_bf16(acc[mt][nt], af[mt][0].y, af[mt][1].y, af[mt][2].y, af[mt][3].y, b0.x, b1.x);
        }
      }
    }
  }

  float hin = 0.5f * (float)h - 0.25f;
  int hi0 = hin < 0.f ? 0 : (int)hin;
  float hf = hin < 0.f ? 0.f : hin - (float)hi0;
  int hi1 = hi0 + 1 < 64 ? hi0 + 1 : 63;

#pragma unroll
  for (int mt = 0; mt < 2; mt++) {
#pragma unroll
    for (int half = 0; half < 2; half++) {
      int o = warpO + mt * 16 + lr + 8 * half;
      const float* xb = xh + (size_t)(b * 256 + o) * 4096;
      const float* r0 = xb + hi0 * 64;
      const float* r1 = xb + hi1 * 64;
      float* orow = out + (size_t)(b * 256 + o) * 16384 + h * 128;
#pragma unroll
      for (int nt = 0; nt < 8; nt++) {
        int w0 = wBase + nt * 8 + 2 * lc;
        float v[2];
#pragma unroll
        for (int j = 0; j < 2; j++) {
          int w = w0 + j;
          float win = 0.5f * (float)w - 0.25f;
          int wi0 = win < 0.f ? 0 : (int)win;
          float wf = win < 0.f ? 0.f : win - (float)wi0;
          int wi1 = wi0 + 1 < 64 ? wi0 + 1 : 63;
          float top = r0[wi0] * (1.f - wf) + r0[wi1] * wf;
          float bot = r1[wi0] * (1.f - wf) + r1[wi1] * wf;
          v[j] = acc[mt][nt][half * 2 + j] + top * (1.f - hf) + bot * hf;
        }
        *(float2*)&orow[w0] = make_float2(v[0], v[1]);
      }
    }
  }
}

// ---------------- launch ----------------
extern "C" void kernel_launch(void* const* d_in, const int* in_sizes, int n_in,
                              void* d_out, int out_size) {
  const float* x_high = (const float*)d_in[0];
  const float* x_low = (const float*)d_in[1];
  const float* w1 = (const float*)d_in[2];
  const float* b1 = (const float*)d_in[3];
  const float* w2 = (const float*)d_in[4];
  const float* b2 = (const float*)d_in[5];
  const float* refine_w = (const float*)d_in[6];
  float* out = (float*)d_out;

  const int SMEM_FFT = 2 * 128 * 129 * 4;                  // 132096 B
  const int SMEM_FUSED = SMEM_FFT + 38 * 134 * 8;          // +40736 = 172832 B
  cudaFuncSetAttribute((const void*)fwd_fft_pair_kernel, cudaFuncAttributeMaxDynamicSharedMemorySize, SMEM_FFT);
  cudaFuncSetAttribute((const void*)inv_fused_kernel, cudaFuncAttributeMaxDynamicSharedMemorySize, SMEM_FUSED);

  wsplit_kernel<<<128, 256>>>(refine_w);
  fwd_fft_pair_kernel<<<1024, 1024, SMEM_FFT>>>(x_low);
  mlp_kernel<<<8, 256>>>(w1, b1, w2, b2);
  bconv_kernel<<<1024, 256>>>();
  inv_fused_kernel<<<1024, 1024, SMEM_FUSED>>>();
  mix_kernel<<<dim3(128, 2, 8), 256>>>(x_high, out);
}

// round 14
// speedup vs baseline: 1.2257x; 1.2257x over previous
#include <cuda_runtime.h>
#include <cuda_bf16.h>
#include <math.h>
#include <stdint.h>

#ifndef M_PI
#define M_PI 3.14159265358979323846
#endif

#define FULLMASK 0xffffffffu

// ---------------- scratch (static device globals; no allocations) ----------------
__device__ float2   g_F[16777216];    // packed spectrum Z = fft2(x1 + i x2), shifted  [1024 pairs][16384]
__device__ float2   g_G[16777216];    // W = combined conv output (packed)             [1024 pairs][16384]
__device__ uint32_t g_Rhi[16777216];  // real(ifft2) bf16 hi, packed channel pairs [B*128][16384]
__device__ uint32_t g_Rlo[16777216];  // residual bf16 lo
__device__ float    g_kern[8 * 49];   // per-batch 7x7 kernel
__device__ uint32_t g_Whi[32768];     // refine_w split: [c2=128][o=256]
__device__ uint32_t g_Wlo[32768];     // residuals

// ---------------- complex helpers ----------------
__device__ __forceinline__ float2 cadd(float2 a, float2 b) { return make_float2(a.x + b.x, a.y + b.y); }
__device__ __forceinline__ float2 csub(float2 a, float2 b) { return make_float2(a.x - b.x, a.y - b.y); }
__device__ __forceinline__ float2 cmul(float2 a, float2 b) {
  return make_float2(a.x * b.x - a.y * b.y, a.x * b.y + a.y * b.x);
}

// ---------------- bf16 split helpers ----------------
__device__ __forceinline__ void split2_bf16(float xe, float xo, uint32_t& hi, uint32_t& lo) {
  __nv_bfloat16 he = __float2bfloat16_rn(xe);
  __nv_bfloat16 ho = __float2bfloat16_rn(xo);
  float re = xe - __bfloat162float(he);
  float ro = xo - __bfloat162float(ho);
  __nv_bfloat16 le = __float2bfloat16_rn(re);
  __nv_bfloat16 lo16 = __float2bfloat16_rn(ro);
  hi = (uint32_t)__bfloat16_as_ushort(he) | ((uint32_t)__bfloat16_as_ushort(ho) << 16);
  lo = (uint32_t)__bfloat16_as_ushort(le) | ((uint32_t)__bfloat16_as_ushort(lo16) << 16);
}

// ---------------- warp-resident 128-pt DIF FFT ----------------
template<int SGN>
__device__ __forceinline__ void make_twiddles(int lane, float2 tw[7]) {
  const float TP = 6.283185307179586f * (float)SGN;
  float fr[7] = { lane / 128.f, (lane + 32) / 128.f, lane / 64.f,
                  (lane & 15) / 32.f, (lane & 7) / 16.f, (lane & 3) / 8.f, (lane & 1) / 4.f };
#pragma unroll
  for (int i = 0; i < 7; i++) {
    float s, c;
    sincosf(TP * fr[i], &s, &c);
    tw[i] = make_float2(c, s);
  }
}

__device__ __forceinline__ void fft128(float2 v[4], const float2 tw[7], int lane) {
  float2 t, u;
  t = v[0]; u = v[2]; v[0] = cadd(t, u); v[2] = cmul(csub(t, u), tw[0]);
  t = v[1]; u = v[3]; v[1] = cadd(t, u); v[3] = cmul(csub(t, u), tw[1]);
  t = v[0]; u = v[1]; v[0] = cadd(t, u); v[1] = cmul(csub(t, u), tw[2]);
  t = v[2]; u = v[3]; v[2] = cadd(t, u); v[3] = cmul(csub(t, u), tw[2]);
#pragma unroll
  for (int hi = 0; hi < 5; hi++) {
    int h = 16 >> hi;
    bool up = (lane & h) != 0;
#pragma unroll
    for (int s = 0; s < 4; s++) {
      float prx = __shfl_xor_sync(FULLMASK, v[s].x, h);
      float pry = __shfl_xor_sync(FULLMASK, v[s].y, h);
      float2 pr = make_float2(prx, pry);
      if (hi < 4) {
        v[s] = up ? cmul(csub(pr, v[s]), tw[3 + hi]) : cadd(v[s], pr);
      } else {
        v[s] = up ? csub(pr, v[s]) : cadd(v[s], pr);
      }
    }
  }
}

__device__ __forceinline__ int bitrev7(int p) { return (int)(__brev((unsigned)p) >> 25); }

// ---------------- forward FFT (channel-pair packed): x_low -> g_F (packed Z) ----------------
__global__ void __launch_bounds__(1024) fwd_fft_pair_kernel(const float* __restrict__ x) {
  extern __shared__ float sm[];
  float* sre = sm;
  float* sim = sm + 128 * 129;
  int pair = blockIdx.x;
  int ch1 = pair * 2, ch2 = ch1 + 1;
  int tid = threadIdx.x;
  int warp = tid >> 5, lane = tid & 31;
  float2 tw[7];
  make_twiddles<-1>(lane, tw);
  const float* x1 = x + (size_t)ch1 * 16384;
  const float* x2 = x + (size_t)ch2 * 16384;

  for (int r = warp; r < 128; r += 32) {
    float2 v[4];
#pragma unroll
    for (int s = 0; s < 4; s++) {
      int c = s * 32 + lane;
      v[s] = make_float2(x1[r * 128 + c] * 0.0078125f, x2[r * 128 + c] * 0.0078125f);
    }
    fft128(v, tw, lane);
#pragma unroll
    for (int s = 0; s < 4; s++) {
      int p = s * 32 + lane;
      int n = bitrev7(p) ^ 64;
      sre[r * 129 + n] = v[s].x;
      sim[r * 129 + n] = v[s].y;
    }
  }
  __syncthreads();
  for (int c = warp; c < 128; c += 32) {
    float2 v[4];
#pragma unroll
    for (int s = 0; s < 4; s++) {
      int p = s * 32 + lane;
      v[s] = make_float2(sre[p * 129 + c], sim[p * 129 + c]);
    }
    fft128(v, tw, lane);
#pragma unroll
    for (int s = 0; s < 4; s++) {
      int p = s * 32 + lane;
      int n = bitrev7(p) ^ 64;
      sre[n * 129 + c] = v[s].x;
      sim[n * 129 + c] = v[s].y;
    }
  }
  __syncthreads();
  float2* Zb = g_F + (size_t)pair * 16384;
  for (int i = tid; i < 16384; i += 1024) {
    int r = i >> 7, c = i & 127;
    Zb[i] = make_float2(sre[r * 129 + c], sim[r * 129 + c]);
  }
}

// ---------------- tiny path: center magnitudes (unpacked from Z) -> MLP -> kernel ----------------
__global__ void __launch_bounds__(256) mlp_kernel(const float* __restrict__ w1, const float* __restrict__ b1,
                                                  const float* __restrict__ w2, const float* __restrict__ b2) {
  int b = blockIdx.x;
  int t = threadIdx.x;
  __shared__ float part[49][4];
  __shared__ float flat[49];
  __shared__ float hbuf[32];
  __shared__ float prm[3];
  __shared__ float kv[49];
  __shared__ float ksum;

  if (t < 196) {
    int p = t >> 2, q = t & 3;
    int i = p / 7, j = p % 7;
    int im = 6 - i, jm = 6 - j;
    const float2* Zb = g_F + ((size_t)(b * 128 + q * 32)) * 16384;
    float s = 0.f;
#pragma unroll 4
    for (int pr = 0; pr < 32; pr++) {
      const float2* Zp = Zb + (size_t)pr * 16384;
      float2 z = Zp[(61 + i) * 128 + (61 + j)];
      float2 zm = Zp[(61 + im) * 128 + (61 + jm)];
      float e1 = z.x + zm.x, e2 = z.y - zm.y;
      float o1 = z.x - zm.x, o2 = z.y + zm.y;
      s += 0.5f * (sqrtf(e1 * e1 + e2 * e2) + sqrtf(o1 * o1 + o2 * o2));
    }
    part[p][q] = s;
  }
  __syncthreads();
  if (t < 49) flat[t] = (part[t][0] + part[t][1] + part[t][2] + part[t][3]) * (1.f / 256.f);
  __syncthreads();
  if (t < 32) {
    float a = b1[t];
#pragma unroll
    for (int i = 0; i < 49; i++) a += flat[i] * w1[t * 49 + i];
    hbuf[t] = fmaxf(a, 0.f);
  }
  __syncthreads();
  if (t < 3) {
    float a = b2[t];
#pragma unroll
    for (int u = 0; u < 32; u++) a += hbuf[u] * w2[t * 32 + u];
    prm[t] = a;
  }
  __syncthreads();
  if (t < 49) {
    float theta = atan2f(prm[0], prm[1]) * 0.5f + (float)M_PI * 0.5f;
    float lam1 = expf(prm[2]);
    float lam2 = 1.f / (lam1 + 1e-8f);
    float ct = cosf(theta), st = sinf(theta);
    int i = t / 7, j = t % 7;
    float yy = (float)(i - 3), xx = (float)(j - 3);
    float xr = xx * ct + yy * st;
    float yr = -xx * st + yy * ct;
    kv[t] = expf(-(xr * xr / (2.f * lam1 * lam1) + yr * yr / (2.f * lam2 * lam2)));
  }
  __syncthreads();
  if (t == 0) {
    float s = 0.f;
    for (int i = 0; i < 49; i++) s += kv[i];
    ksum = s;
  }
  __syncthreads();
  if (t < 49) g_kern[b * 49 + t] = kv[t] / (ksum + 1e-8f);
}

// ---------------- circular conv (interior-exact): Z -> W, no boundary logic at all ----------------
__global__ void __launch_bounds__(256) cconv_kernel() {
  __shared__ float2 tile[22][134];
  __shared__ float kc[49];
  int pair = blockIdx.x;          // 0..1023
  int b = pair >> 7;
  int rBase = blockIdx.y * 16;
  int tid = threadIdx.x;
  if (tid < 49) kc[tid] = g_kern[b * 49 + tid];
  const float2* Zb = g_F + (size_t)pair * 16384;
  for (int idx = tid; idx < 22 * 134; idx += 256) {
    int tr = idx / 134, tc = idx % 134;
    int gr = (rBase - 3 + tr) & 127;   // circular halo
    int gc = (tc - 3) & 127;
    tile[tr][tc] = Zb[gr * 128 + gc];
  }
  __syncthreads();
  int w = tid & 127, rg = tid >> 7;
  float2* Wb = g_G + (size_t)pair * 16384;
#pragma unroll
  for (int rr = 0; rr < 8; rr++) {
    int rl = rg * 8 + rr;
    float sre = 0.f, simv = 0.f;
#pragma unroll
    for (int dy = 0; dy < 7; dy++)
#pragma unroll
      for (int dx = 0; dx < 7; dx++) {
        float2 in = tile[rl + dy][w + dx];
        float k = kc[dy * 7 + dx];
        sre += in.x * k;
        simv += in.y * k;
      }
    Wb[(rBase + rl) * 128 + w] = make_float2(sre, simv);
  }
}

// ---------------- boundary fixup: recompute 1743-pixel frame with exact pad/mirror weights ----------------
// W(n) = sum_D k(D) * Z((n+D) mod 128) * 0.5*(a1*a2 + b1*b2)
//   a(n,d) = [0 <= n+d <= 127]                 (zero-pad indicator)
//   b(n,d) = n>=1 ? [1 <= n+d <= 128] : [d<=0] (mirror indicator)
__global__ void __launch_bounds__(256) bconv_kernel() {
  __shared__ float kc[49];
  int pair = blockIdx.x;          // 0..1023
  int b = pair >> 7;
  int tid = threadIdx.x;
  if (tid < 49) kc[tid] = g_kern[b * 49 + tid];
  __syncthreads();
  const float2* Zb = g_F + (size_t)pair * 16384;
  float2* Wb = g_G + (size_t)pair * 16384;
  // frame: rows {0..3,125..127} x all cols (896) + rows 4..124 x cols {0..3,125..127} (847)
  for (int idx = tid; idx < 1743; idx += 256) {
    int n1, n2;
    if (idx < 896) {
      int r = idx >> 7;
      n1 = (r < 4) ? r : (121 + r);     // 0..3, 125..127
      n2 = idx & 127;
    } else {
      int j = idx - 896;
      n1 = 4 + j / 7;                   // 4..124
      int c = j % 7;
      n2 = (c < 4) ? c : (121 + c);     // 0..3, 125..127
    }
    float wy[7], wz[7], vy[7], vz[7];   // per-axis a/b indicators
#pragma unroll
    for (int d = 0; d < 7; d++) {
      int dd = d - 3;
      int j1 = n1 + dd, j2 = n2 + dd;
      wy[d] = (j1 >= 0 && j1 <= 127) ? 1.f : 0.f;
      vy[d] = ((n1 >= 1) ? (j1 >= 1 && j1 <= 128) : (dd <= 0)) ? 1.f : 0.f;
      wz[d] = (j2 >= 0 && j2 <= 127) ? 1.f : 0.f;
      vz[d] = ((n2 >= 1) ? (j2 >= 1 && j2 <= 128) : (dd <= 0)) ? 1.f : 0.f;
    }
    float sre = 0.f, simv = 0.f;
#pragma unroll
    for (int dy = 0; dy < 7; dy++) {
      int r = (n1 + dy - 3) & 127;
      const float2* Zr = Zb + r * 128;
#pragma unroll
      for (int dx = 0; dx < 7; dx++) {
        float wt = 0.5f * (wy[dy] * wz[dx] + vy[dy] * vz[dx]) * kc[dy * 7 + dx];
        float2 in = Zr[(n2 + dx - 3) & 127];
        sre += in.x * wt;
        simv += in.y * wt;
      }
    }
    Wb[n1 * 128 + n2] = make_float2(sre, simv);
  }
}

// ---------------- inverse FFT: W -> g_Rhi/g_Rlo (bf16 split) ----------------
__global__ void __launch_bounds__(1024) inv_fft_pair_kernel() {
  extern __shared__ float sm[];
  float* sre = sm;
  float* sim = sm + 128 * 129;
  int pair = blockIdx.x;
  int tid = threadIdx.x;
  int warp = tid >> 5, lane = tid & 31;
  float2 tw[7];
  make_twiddles<1>(lane, tw);
  const float2* Wb = g_G + (size_t)pair * 16384;

  for (int r = warp; r < 128; r += 32) {
    float2 v[4];
#pragma unroll
    for (int s = 0; s < 4; s++) {
      int cidx = (s * 32 + lane) ^ 64;      // ifftshift on cols
      float2 g = Wb[r * 128 + cidx];
      v[s] = make_float2(g.x * 0.0078125f, g.y * 0.0078125f);   // ortho 1/128
    }
    fft128(v, tw, lane);
#pragma unroll
    for (int s = 0; s < 4; s++) {
      int p = s * 32 + lane;
      int n = bitrev7(p);
      sre[r * 129 + n] = v[s].x;
      sim[r * 129 + n] = v[s].y;
    }
  }
  __syncthreads();
  for (int c = warp; c < 128; c += 32) {
    float2 v[4];
#pragma unroll
    for (int s = 0; s < 4; s++) {
      int ridx = (s * 32 + lane) ^ 64;      // ifftshift on rows
      v[s] = make_float2(sre[ridx * 129 + c], sim[ridx * 129 + c]);
    }
    fft128(v, tw, lane);
#pragma unroll
    for (int s = 0; s < 4; s++) {
      int p = s * 32 + lane;
      int n = bitrev7(p);
      sre[n * 129 + c] = v[s].x;
      sim[n * 129 + c] = v[s].y;
    }
  }
  __syncthreads();
  uint32_t* Rh = g_Rhi + (size_t)pair * 16384;
  uint32_t* Rl = g_Rlo + (size_t)pair * 16384;
  for (int i = tid; i < 16384; i += 1024) {
    int r = i >> 7, c = i & 127;
    uint32_t hi, lo;
    split2_bf16(sre[r * 129 + c], sim[r * 129 + c], hi, lo);
    Rh[i] = hi;
    Rl[i] = lo;
  }
}

// ---------------- weight prep: refine_w -> bf16-split packed channel pairs ----------------
__global__ void __launch_bounds__(256) wsplit_kernel(const float* __restrict__ W) {
  int idx = blockIdx.x * 256 + threadIdx.x;   // 0..32767
  int c2 = idx & 127, o = idx >> 7;
  float xe = W[o * 256 + 2 * c2];
  float xo = W[o * 256 + 2 * c2 + 1];
  uint32_t hi, lo;
  split2_bf16(xe, xo, hi, lo);
  g_Whi[c2 * 256 + o] = hi;
  g_Wlo[c2 * 256 + o] = lo;
}

// ---------------- bf16 MMA helper ----------------
__device__ __forceinline__ void mma_bf16(float* c, uint32_t a0, uint32_t a1, uint32_t a2, uint32_t a3,
                                         uint32_t b0, uint32_t b1) {
  asm volatile(
      "mma.sync.aligned.m16n8k16.row.col.f32.bf16.bf16.f32 "
      "{%0,%1,%2,%3}, {%4,%5,%6,%7}, {%8,%9}, {%0,%1,%2,%3};"
      : "+f"(c[0]), "+f"(c[1]), "+f"(c[2]), "+f"(c[3])
      : "r"(a0), "r"(a1), "r"(a2), "r"(a3), "r"(b0), "r"(b1));
}

// ---------------- channel mix GEMM (3-term bf16) + bilinear epilogue ----------------
// Block: 8 warps cover FULL o=256 (warp tile 32o x 64w); block w-tile 64 (grid y = w half).
// Removes the duplicated Rhi/Rlo reads of the previous 128-o split.
__global__ void __launch_bounds__(256, 2) mix_kernel(const float* __restrict__ xh, float* __restrict__ out) {
  int b = blockIdx.z;
  int h = blockIdx.x;
  int wBase = blockIdx.y * 64;
  int tid = threadIdx.x;
  int warp = tid >> 5, lane = tid & 31;
  int lr = lane >> 2, lc = lane & 3;
  int warpO = warp * 32;

  __shared__ uint2 As[16][264];   // [k2][o 0..255]  {hi,lo}
  __shared__ uint2 Bs[16][72];    // [k2][w 0..63]

  float acc[2][8][4];
#pragma unroll
  for (int mt = 0; mt < 2; mt++)
#pragma unroll
    for (int nt = 0; nt < 8; nt++)
#pragma unroll
      for (int q = 0; q < 4; q++) acc[mt][nt][q] = 0.f;

  const uint32_t* RhB = g_Rhi + (size_t)b * 128 * 16384 + h * 128 + wBase;
  const uint32_t* RlB = g_Rlo + (size_t)b * 128 * 16384 + h * 128 + wBase;

  for (int kb = 0; kb < 8; kb++) {
    __syncthreads();
#pragma unroll
    for (int it = 0; it < 8; it++) {        // A: 16 k2 x 128 o2 = 2048 items
      int item = it * 256 + tid;
      int o2 = item & 127;
      int k2 = item >> 7;
      uint2 ah = *(const uint2*)&g_Whi[(kb * 16 + k2) * 256 + o2 * 2];
      uint2 al = *(const uint2*)&g_Wlo[(kb * 16 + k2) * 256 + o2 * 2];
      *(uint4*)&As[k2][o2 * 2] = make_uint4(ah.x, al.x, ah.y, al.y);
    }
#pragma unroll
    for (int it = 0; it < 2; it++) {        // B: 16 k2 x 32 w2 = 512 items
      int item = it * 256 + tid;
      int w2 = item & 31;
      int k2 = item >> 5;
      uint2 bh = *(const uint2*)&RhB[(size_t)(kb * 16 + k2) * 16384 + w2 * 2];
      uint2 bl = *(const uint2*)&RlB[(size_t)(kb * 16 + k2) * 16384 + w2 * 2];
      *(uint4*)&Bs[k2][w2 * 2] = make_uint4(bh.x, bl.x, bh.y, bl.y);
    }
    __syncthreads();
#pragma unroll
    for (int s = 0; s < 2; s++) {
      uint2 af[2][4];
#pragma unroll
      for (int mt = 0; mt < 2; mt++) {
#pragma unroll
        for (int rg = 0; rg < 4; rg++) {
          int k2 = s * 8 + lc + 4 * (rg >> 1);
          int o = warpO + mt * 16 + lr + 8 * (rg & 1);
          af[mt][rg] = As[k2][o];
        }
      }
      const uint2* bRow0 = &Bs[s * 8 + lc][lr];
      const uint2* bRow1 = &Bs[s * 8 + lc + 4][lr];
#pragma unroll
      for (int nt = 0; nt < 8; nt++) {
        uint2 b0 = bRow0[nt * 8];
        uint2 b1 = bRow1[nt * 8];
#pragma unroll
        for (int mt = 0; mt < 2; mt++) {
          mma_bf16(acc[mt][nt], af[mt][0].x, af[mt][1].x, af[mt][2].x, af[mt][3].x, b0.x, b1.x);
          mma_bf16(acc[mt][nt], af[mt][0].x, af[mt][1].x, af[mt][2].x, af[mt][3].x, b0.y, b1.y);
          mma_bf16(acc[mt][nt], af[mt][0].y, af[mt][1].y, af[mt][2].y, af[mt][3].y, b0.x, b1.x);
        }
      }
    }
  }

  float hin = 0.5f * (float)h - 0.25f;
  int hi0 = hin < 0.f ? 0 : (int)hin;
  float hf = hin < 0.f ? 0.f : hin - (float)hi0;
  int hi1 = hi0 + 1 < 64 ? hi0 + 1 : 63;

#pragma unroll
  for (int mt = 0; mt < 2; mt++) {
#pragma unroll
    for (int half = 0; half < 2; half++) {
      int o = warpO + mt * 16 + lr + 8 * half;
      const float* xb = xh + (size_t)(b * 256 + o) * 4096;
      const float* r0 = xb + hi0 * 64;
      const float* r1 = xb + hi1 * 64;
      float* orow = out + (size_t)(b * 256 + o) * 16384 + h * 128;
#pragma unroll
      for (int nt = 0; nt < 8; nt++) {
        int w0 = wBase + nt * 8 + 2 * lc;
        float v[2];
#pragma unroll
        for (int j = 0; j < 2; j++) {
          int w = w0 + j;
          float win = 0.5f * (float)w - 0.25f;
          int wi0 = win < 0.f ? 0 : (int)win;
          float wf = win < 0.f ? 0.f : win - (float)wi0;
          int wi1 = wi0 + 1 < 64 ? wi0 + 1 : 63;
          float top = r0[wi0] * (1.f - wf) + r0[wi1] * wf;
          float bot = r1[wi0] * (1.f - wf) + r1[wi1] * wf;
          v[j] = acc[mt][nt][half * 2 + j] + top * (1.f - hf) + bot * hf;
        }
        *(float2*)&orow[w0] = make_float2(v[0], v[1]);
      }
    }
  }
}

// ---------------- launch ----------------
extern "C" void kernel_launch(void* const* d_in, const int* in_sizes, int n_in,
                              void* d_out, int out_size) {
  const float* x_high = (const float*)d_in[0];
  const float* x_low = (const float*)d_in[1];
  const float* w1 = (const float*)d_in[2];
  const float* b1 = (const float*)d_in[3];
  const float* w2 = (const float*)d_in[4];
  const float* b2 = (const float*)d_in[5];
  const float* refine_w = (const float*)d_in[6];
  float* out = (float*)d_out;

  const int SMEM_FFT = 2 * 128 * 129 * 4;  // 132096 B
  cudaFuncSetAttribute((const void*)fwd_fft_pair_kernel, cudaFuncAttributeMaxDynamicSharedMemorySize, SMEM_FFT);
  cudaFuncSetAttribute((const void*)inv_fft_pair_kernel, cudaFuncAttributeMaxDynamicSharedMemorySize, SMEM_FFT);

  wsplit_kernel<<<128, 256>>>(refine_w);
  fwd_fft_pair_kernel<<<1024, 1024, SMEM_FFT>>>(x_low);
  mlp_kernel<<<8, 256>>>(w1, b1, w2, b2);
  cconv_kernel<<<dim3(1024, 8), 256>>>();
  bconv_kernel<<<1024, 256>>>();
  inv_fft_pair_kernel<<<1024, 1024, SMEM_FFT>>>();
  mix_kernel<<<dim3(128, 2, 8), 256>>>(x_high, out);
}

// round 15
// speedup vs baseline: 1.3606x; 1.1101x over previous
#include <cuda_runtime.h>
#include <cuda_bf16.h>
#include <math.h>
#include <stdint.h>

#ifndef M_PI
#define M_PI 3.14159265358979323846
#endif

#define FULLMASK 0xffffffffu

// ---------------- scratch (static device globals; no allocations) ----------------
__device__ float2   g_F[16777216];    // packed spectrum Z = fft2(x1 + i x2), shifted  [1024 pairs][16384]
__device__ float2   g_G[16777216];    // W = combined conv output (packed)             [1024 pairs][16384]
__device__ uint32_t g_Rhi[16777216];  // real(ifft2) bf16 hi, packed channel pairs [B*128][16384]
__device__ uint32_t g_Rlo[16777216];  // residual bf16 lo
__device__ float    g_kern[8 * 49];   // per-batch 7x7 kernel
__device__ uint32_t g_Whi[32768];     // refine_w split: [c2=128][o=256]
__device__ uint32_t g_Wlo[32768];     // residuals

// ---------------- complex helpers ----------------
__device__ __forceinline__ float2 cadd(float2 a, float2 b) { return make_float2(a.x + b.x, a.y + b.y); }
__device__ __forceinline__ float2 csub(float2 a, float2 b) { return make_float2(a.x - b.x, a.y - b.y); }
__device__ __forceinline__ float2 cmul(float2 a, float2 b) {
  return make_float2(a.x * b.x - a.y * b.y, a.x * b.y + a.y * b.x);
}

// ---------------- bf16 split helpers ----------------
__device__ __forceinline__ void split2_bf16(float xe, float xo, uint32_t& hi, uint32_t& lo) {
  __nv_bfloat16 he = __float2bfloat16_rn(xe);
  __nv_bfloat16 ho = __float2bfloat16_rn(xo);
  float re = xe - __bfloat162float(he);
  float ro = xo - __bfloat162float(ho);
  __nv_bfloat16 le = __float2bfloat16_rn(re);
  __nv_bfloat16 lo16 = __float2bfloat16_rn(ro);
  hi = (uint32_t)__bfloat16_as_ushort(he) | ((uint32_t)__bfloat16_as_ushort(ho) << 16);
  lo = (uint32_t)__bfloat16_as_ushort(le) | ((uint32_t)__bfloat16_as_ushort(lo16) << 16);
}

// ---------------- cp.async helpers ----------------
__device__ __forceinline__ void cp_async8(void* sptr, const void* gptr) {
  uint32_t sa = (uint32_t)__cvta_generic_to_shared(sptr);
  asm volatile("cp.async.ca.shared.global [%0], [%1], 8;" :: "r"(sa), "l"(gptr));
}
__device__ __forceinline__ void cp_commit() {
  asm volatile("cp.async.commit_group;" ::: "memory");
}
template <int N>
__device__ __forceinline__ void cp_wait_group() {
  asm volatile("cp.async.wait_group %0;" :: "n"(N) : "memory");
}

// ---------------- warp-resident 128-pt DIF FFT ----------------
template<int SGN>
__device__ __forceinline__ void make_twiddles(int lane, float2 tw[7]) {
  const float TP = 6.283185307179586f * (float)SGN;
  float fr[7] = { lane / 128.f, (lane + 32) / 128.f, lane / 64.f,
                  (lane & 15) / 32.f, (lane & 7) / 16.f, (lane & 3) / 8.f, (lane & 1) / 4.f };
#pragma unroll
  for (int i = 0; i < 7; i++) {
    float s, c;
    sincosf(TP * fr[i], &s, &c);
    tw[i] = make_float2(c, s);
  }
}

__device__ __forceinline__ void fft128(float2 v[4], const float2 tw[7], int lane) {
  float2 t, u;
  t = v[0]; u = v[2]; v[0] = cadd(t, u); v[2] = cmul(csub(t, u), tw[0]);
  t = v[1]; u = v[3]; v[1] = cadd(t, u); v[3] = cmul(csub(t, u), tw[1]);
  t = v[0]; u = v[1]; v[0] = cadd(t, u); v[1] = cmul(csub(t, u), tw[2]);
  t = v[2]; u = v[3]; v[2] = cadd(t, u); v[3] = cmul(csub(t, u), tw[2]);
#pragma unroll
  for (int hi = 0; hi < 5; hi++) {
    int h = 16 >> hi;
    bool up = (lane & h) != 0;
#pragma unroll
    for (int s = 0; s < 4; s++) {
      float prx = __shfl_xor_sync(FULLMASK, v[s].x, h);
      float pry = __shfl_xor_sync(FULLMASK, v[s].y, h);
      float2 pr = make_float2(prx, pry);
      if (hi < 4) {
        v[s] = up ? cmul(csub(pr, v[s]), tw[3 + hi]) : cadd(v[s], pr);
      } else {
        v[s] = up ? csub(pr, v[s]) : cadd(v[s], pr);
      }
    }
  }
}

__device__ __forceinline__ int bitrev7(int p) { return (int)(__brev((unsigned)p) >> 25); }

// ---------------- forward FFT (channel-pair packed): x_low -> g_F (packed Z) ----------------
__global__ void __launch_bounds__(1024) fwd_fft_pair_kernel(const float* __restrict__ x) {
  extern __shared__ float sm[];
  float* sre = sm;
  float* sim = sm + 128 * 129;
  int pair = blockIdx.x;
  int ch1 = pair * 2, ch2 = ch1 + 1;
  int tid = threadIdx.x;
  int warp = tid >> 5, lane = tid & 31;
  float2 tw[7];
  make_twiddles<-1>(lane, tw);
  const float* x1 = x + (size_t)ch1 * 16384;
  const float* x2 = x + (size_t)ch2 * 16384;

  for (int r = warp; r < 128; r += 32) {
    float2 v[4];
#pragma unroll
    for (int s = 0; s < 4; s++) {
      int c = s * 32 + lane;
      v[s] = make_float2(x1[r * 128 + c] * 0.0078125f, x2[r * 128 + c] * 0.0078125f);
    }
    fft128(v, tw, lane);
#pragma unroll
    for (int s = 0; s < 4; s++) {
      int p = s * 32 + lane;
      int n = bitrev7(p) ^ 64;
      sre[r * 129 + n] = v[s].x;
      sim[r * 129 + n] = v[s].y;
    }
  }
  __syncthreads();
  for (int c = warp; c < 128; c += 32) {
    float2 v[4];
#pragma unroll
    for (int s = 0; s < 4; s++) {
      int p = s * 32 + lane;
      v[s] = make_float2(sre[p * 129 + c], sim[p * 129 + c]);
    }
    fft128(v, tw, lane);
#pragma unroll
    for (int s = 0; s < 4; s++) {
      int p = s * 32 + lane;
      int n = bitrev7(p) ^ 64;
      sre[n * 129 + c] = v[s].x;
      sim[n * 129 + c] = v[s].y;
    }
  }
  __syncthreads();
  float2* Zb = g_F + (size_t)pair * 16384;
  for (int i = tid; i < 16384; i += 1024) {
    int r = i >> 7, c = i & 127;
    Zb[i] = make_float2(sre[r * 129 + c], sim[r * 129 + c]);
  }
}

// ---------------- tiny path: center magnitudes (unpacked from Z) -> MLP -> kernel ----------------
__global__ void __launch_bounds__(256) mlp_kernel(const float* __restrict__ w1, const float* __restrict__ b1,
                                                  const float* __restrict__ w2, const float* __restrict__ b2) {
  int b = blockIdx.x;
  int t = threadIdx.x;
  __shared__ float part[49][4];
  __shared__ float flat[49];
  __shared__ float hbuf[32];
  __shared__ float prm[3];
  __shared__ float kv[49];
  __shared__ float ksum;

  if (t < 196) {
    int p = t >> 2, q = t & 3;
    int i = p / 7, j = p % 7;
    int im = 6 - i, jm = 6 - j;
    const float2* Zb = g_F + ((size_t)(b * 128 + q * 32)) * 16384;
    float s = 0.f;
#pragma unroll 4
    for (int pr = 0; pr < 32; pr++) {
      const float2* Zp = Zb + (size_t)pr * 16384;
      float2 z = Zp[(61 + i) * 128 + (61 + j)];
      float2 zm = Zp[(61 + im) * 128 + (61 + jm)];
      float e1 = z.x + zm.x, e2 = z.y - zm.y;
      float o1 = z.x - zm.x, o2 = z.y + zm.y;
      s += 0.5f * (sqrtf(e1 * e1 + e2 * e2) + sqrtf(o1 * o1 + o2 * o2));
    }
    part[p][q] = s;
  }
  __syncthreads();
  if (t < 49) flat[t] = (part[t][0] + part[t][1] + part[t][2] + part[t][3]) * (1.f / 256.f);
  __syncthreads();
  if (t < 32) {
    float a = b1[t];
#pragma unroll
    for (int i = 0; i < 49; i++) a += flat[i] * w1[t * 49 + i];
    hbuf[t] = fmaxf(a, 0.f);
  }
  __syncthreads();
  if (t < 3) {
    float a = b2[t];
#pragma unroll
    for (int u = 0; u < 32; u++) a += hbuf[u] * w2[t * 32 + u];
    prm[t] = a;
  }
  __syncthreads();
  if (t < 49) {
    float theta = atan2f(prm[0], prm[1]) * 0.5f + (float)M_PI * 0.5f;
    float lam1 = expf(prm[2]);
    float lam2 = 1.f / (lam1 + 1e-8f);
    float ct = cosf(theta), st = sinf(theta);
    int i = t / 7, j = t % 7;
    float yy = (float)(i - 3), xx = (float)(j - 3);
    float xr = xx * ct + yy * st;
    float yr = -xx * st + yy * ct;
    kv[t] = expf(-(xr * xr / (2.f * lam1 * lam1) + yr * yr / (2.f * lam2 * lam2)));
  }
  __syncthreads();
  if (t == 0) {
    float s = 0.f;
    for (int i = 0; i < 49; i++) s += kv[i];
    ksum = s;
  }
  __syncthreads();
  if (t < 49) g_kern[b * 49 + t] = kv[t] / (ksum + 1e-8f);
}

// ---------------- circular conv (interior-exact): Z -> W, no boundary logic at all ----------------
__global__ void __launch_bounds__(256) cconv_kernel() {
  __shared__ float2 tile[22][134];
  __shared__ float kc[49];
  int pair = blockIdx.x;          // 0..1023
  int b = pair >> 7;
  int rBase = blockIdx.y * 16;
  int tid = threadIdx.x;
  if (tid < 49) kc[tid] = g_kern[b * 49 + tid];
  const float2* Zb = g_F + (size_t)pair * 16384;
  for (int idx = tid; idx < 22 * 134; idx += 256) {
    int tr = idx / 134, tc = idx % 134;
    int gr = (rBase - 3 + tr) & 127;   // circular halo
    int gc = (tc - 3) & 127;
    tile[tr][tc] = Zb[gr * 128 + gc];
  }
  __syncthreads();
  int w = tid & 127, rg = tid >> 7;
  float2* Wb = g_G + (size_t)pair * 16384;
#pragma unroll
  for (int rr = 0; rr < 8; rr++) {
    int rl = rg * 8 + rr;
    float sre = 0.f, simv = 0.f;
#pragma unroll
    for (int dy = 0; dy < 7; dy++)
#pragma unroll
      for (int dx = 0; dx < 7; dx++) {
        float2 in = tile[rl + dy][w + dx];
        float k = kc[dy * 7 + dx];
        sre += in.x * k;
        simv += in.y * k;
      }
    Wb[(rBase + rl) * 128 + w] = make_float2(sre, simv);
  }
}

// ---------------- boundary fixup: 1743-pixel frame with exact pad/mirror weights ----------------
// grid (1024 pairs, 7 slices) — one 256-px slice per block for latency hiding (96-reg kernel).
__global__ void __launch_bounds__(256) bconv_kernel() {
  __shared__ float kc[49];
  int pair = blockIdx.x;          // 0..1023
  int b = pair >> 7;
  int tid = threadIdx.x;
  if (tid < 49) kc[tid] = g_kern[b * 49 + tid];
  __syncthreads();
  const float2* Zb = g_F + (size_t)pair * 16384;
  float2* Wb = g_G + (size_t)pair * 16384;
  int idx = blockIdx.y * 256 + tid;
  if (idx < 1743) {
    int n1, n2;
    if (idx < 896) {
      int r = idx >> 7;
      n1 = (r < 4) ? r : (121 + r);     // 0..3, 125..127
      n2 = idx & 127;
    } else {
      int j = idx - 896;
      n1 = 4 + j / 7;                   // 4..124
      int c = j % 7;
      n2 = (c < 4) ? c : (121 + c);     // 0..3, 125..127
    }
    float wy[7], wz[7], vy[7], vz[7];   // per-axis a/b indicators
#pragma unroll
    for (int d = 0; d < 7; d++) {
      int dd = d - 3;
      int j1 = n1 + dd, j2 = n2 + dd;
      wy[d] = (j1 >= 0 && j1 <= 127) ? 1.f : 0.f;
      vy[d] = ((n1 >= 1) ? (j1 >= 1 && j1 <= 128) : (dd <= 0)) ? 1.f : 0.f;
      wz[d] = (j2 >= 0 && j2 <= 127) ? 1.f : 0.f;
      vz[d] = ((n2 >= 1) ? (j2 >= 1 && j2 <= 128) : (dd <= 0)) ? 1.f : 0.f;
    }
    float sre = 0.f, simv = 0.f;
#pragma unroll
    for (int dy = 0; dy < 7; dy++) {
      int r = (n1 + dy - 3) & 127;
      const float2* Zr = Zb + r * 128;
#pragma unroll
      for (int dx = 0; dx < 7; dx++) {
        float wt = 0.5f * (wy[dy] * wz[dx] + vy[dy] * vz[dx]) * kc[dy * 7 + dx];
        float2 in = Zr[(n2 + dx - 3) & 127];
        sre += in.x * wt;
        simv += in.y * wt;
      }
    }
    Wb[n1 * 128 + n2] = make_float2(sre, simv);
  }
}

// ---------------- inverse FFT: W -> g_Rhi/g_Rlo (bf16 split) ----------------
__global__ void __launch_bounds__(1024) inv_fft_pair_kernel() {
  extern __shared__ float sm[];
  float* sre = sm;
  float* sim = sm + 128 * 129;
  int pair = blockIdx.x;
  int tid = threadIdx.x;
  int warp = tid >> 5, lane = tid & 31;
  float2 tw[7];
  make_twiddles<1>(lane, tw);
  const float2* Wb = g_G + (size_t)pair * 16384;

  for (int r = warp; r < 128; r += 32) {
    float2 v[4];
#pragma unroll
    for (int s = 0; s < 4; s++) {
      int cidx = (s * 32 + lane) ^ 64;      // ifftshift on cols
      float2 g = Wb[r * 128 + cidx];
      v[s] = make_float2(g.x * 0.0078125f, g.y * 0.0078125f);   // ortho 1/128
    }
    fft128(v, tw, lane);
#pragma unroll
    for (int s = 0; s < 4; s++) {
      int p = s * 32 + lane;
      int n = bitrev7(p);
      sre[r * 129 + n] = v[s].x;
      sim[r * 129 + n] = v[s].y;
    }
  }
  __syncthreads();
  for (int c = warp; c < 128; c += 32) {
    float2 v[4];
#pragma unroll
    for (int s = 0; s < 4; s++) {
      int ridx = (s * 32 + lane) ^ 64;      // ifftshift on rows
      v[s] = make_float2(sre[ridx * 129 + c], sim[ridx * 129 + c]);
    }
    fft128(v, tw, lane);
#pragma unroll
    for (int s = 0; s < 4; s++) {
      int p = s * 32 + lane;
      int n = bitrev7(p);
      sre[n * 129 + c] = v[s].x;
      sim[n * 129 + c] = v[s].y;
    }
  }
  __syncthreads();
  uint32_t* Rh = g_Rhi + (size_t)pair * 16384;
  uint32_t* Rl = g_Rlo + (size_t)pair * 16384;
  for (int i = tid; i < 16384; i += 1024) {
    int r = i >> 7, c = i & 127;
    uint32_t hi, lo;
    split2_bf16(sre[r * 129 + c], sim[r * 129 + c], hi, lo);
    Rh[i] = hi;
    Rl[i] = lo;
  }
}

// ---------------- weight prep: refine_w -> bf16-split packed channel pairs ----------------
__global__ void __launch_bounds__(256) wsplit_kernel(const float* __restrict__ W) {
  int idx = blockIdx.x * 256 + threadIdx.x;   // 0..32767
  int c2 = idx & 127, o = idx >> 7;
  float xe = W[o * 256 + 2 * c2];
  float xo = W[o * 256 + 2 * c2 + 1];
  uint32_t hi, lo;
  split2_bf16(xe, xo, hi, lo);
  g_Whi[c2 * 256 + o] = hi;
  g_Wlo[c2 * 256 + o] = lo;
}

// ---------------- bf16 MMA helper ----------------
__device__ __forceinline__ void mma_bf16(float* c, uint32_t a0, uint32_t a1, uint32_t a2, uint32_t a3,
                                         uint32_t b0, uint32_t b1) {
  asm volatile(
      "mma.sync.aligned.m16n8k16.row.col.f32.bf16.bf16.f32 "
      "{%0,%1,%2,%3}, {%4,%5,%6,%7}, {%8,%9}, {%0,%1,%2,%3};"
      : "+f"(c[0]), "+f"(c[1]), "+f"(c[2]), "+f"(c[3])
      : "r"(a0), "r"(a1), "r"(a2), "r"(a3), "r"(b0), "r"(b1));
}

// ---------------- channel mix GEMM (3-term bf16, cp.async double-buffered) + bilinear epilogue ----------------
// 8 warps cover full o=256 (warp 32o x 64w); block w-tile 64. hi/lo in separate smem arrays.
// A row stride 264 u32 (bank = 8*lc + lr, conflict-free); B row stride 88 u32 (bank = 24*lc + lr).
#define MIX_SA 4224   // 16*264 per stage
#define MIX_SB 1408   // 16*88  per stage
__global__ void __launch_bounds__(256, 2) mix_kernel(const float* __restrict__ xh, float* __restrict__ out) {
  extern __shared__ uint32_t smx[];
  uint32_t* AsHi = smx;                 // [2][16][264]
  uint32_t* AsLo = smx + 2 * MIX_SA;    // [2][16][264]
  uint32_t* BsHi = smx + 4 * MIX_SA;    // [2][16][88]
  uint32_t* BsLo = smx + 4 * MIX_SA + 2 * MIX_SB;

  int b = blockIdx.z;
  int h = blockIdx.x;
  int wBase = blockIdx.y * 64;
  int tid = threadIdx.x;
  int warp = tid >> 5, lane = tid & 31;
  int lr = lane >> 2, lc = lane & 3;
  int warpO = warp * 32;

  float acc[2][8][4];
#pragma unroll
  for (int mt = 0; mt < 2; mt++)
#pragma unroll
    for (int nt = 0; nt < 8; nt++)
#pragma unroll
      for (int q = 0; q < 4; q++) acc[mt][nt][q] = 0.f;

  const uint32_t* RhB = g_Rhi + (size_t)b * 128 * 16384 + h * 128 + wBase;
  const uint32_t* RlB = g_Rlo + (size_t)b * 128 * 16384 + h * 128 + wBase;

  // stage loader: kb block -> stage st
  auto load_stage = [&](int st, int kb) {
#pragma unroll
    for (int it = 0; it < 8; it++) {        // A: 16 k2 x 128 o2 (8B each)
      int item = it * 256 + tid;
      int o2 = item & 127;
      int k2 = item >> 7;
      cp_async8(&AsHi[st * MIX_SA + k2 * 264 + o2 * 2], &g_Whi[(kb * 16 + k2) * 256 + o2 * 2]);
      cp_async8(&AsLo[st * MIX_SA + k2 * 264 + o2 * 2], &g_Wlo[(kb * 16 + k2) * 256 + o2 * 2]);
    }
#pragma unroll
    for (int it = 0; it < 2; it++) {        // B: 16 k2 x 32 w2 (8B each)
      int item = it * 256 + tid;
      int w2 = item & 31;
      int k2 = item >> 5;
      cp_async8(&BsHi[st * MIX_SB + k2 * 88 + w2 * 2], &RhB[(size_t)(kb * 16 + k2) * 16384 + w2 * 2]);
      cp_async8(&BsLo[st * MIX_SB + k2 * 88 + w2 * 2], &RlB[(size_t)(kb * 16 + k2) * 16384 + w2 * 2]);
    }
    cp_commit();
  };

  load_stage(0, 0);
  for (int kb = 0; kb < 8; kb++) {
    int st = kb & 1;
    if (kb + 1 < 8) {
      load_stage(1 - st, kb + 1);
      cp_wait_group<1>();     // stage st resident; next stage may still be in flight
    } else {
      cp_wait_group<0>();
    }
    __syncthreads();
    const uint32_t* aH = AsHi + st * MIX_SA;
    const uint32_t* aL = AsLo + st * MIX_SA;
    const uint32_t* bH = BsHi + st * MIX_SB;
    const uint32_t* bL = BsLo + st * MIX_SB;
#pragma unroll
    for (int s = 0; s < 2; s++) {
      uint32_t ahi[2][4], alo[2][4];
#pragma unroll
      for (int mt = 0; mt < 2; mt++) {
#pragma unroll
        for (int rg = 0; rg < 4; rg++) {
          int k2 = s * 8 + lc + 4 * (rg >> 1);
          int o = warpO + mt * 16 + lr + 8 * (rg & 1);
          ahi[mt][rg] = aH[k2 * 264 + o];
          alo[mt][rg] = aL[k2 * 264 + o];
        }
      }
      int kr0 = (s * 8 + lc) * 88 + lr;
      int kr1 = (s * 8 + lc + 4) * 88 + lr;
#pragma unroll
      for (int nt = 0; nt < 8; nt++) {
        uint32_t b0h = bH[kr0 + nt * 8];
        uint32_t b1h = bH[kr1 + nt * 8];
        uint32_t b0l = bL[kr0 + nt * 8];
        uint32_t b1l = bL[kr1 + nt * 8];
#pragma unroll
        for (int mt = 0; mt < 2; mt++) {
          mma_bf16(acc[mt][nt], ahi[mt][0], ahi[mt][1], ahi[mt][2], ahi[mt][3], b0h, b1h);
          mma_bf16(acc[mt][nt], ahi[mt][0], ahi[mt][1], ahi[mt][2], ahi[mt][3], b0l, b1l);
          mma_bf16(acc[mt][nt], alo[mt][0], alo[mt][1], alo[mt][2], alo[mt][3], b0h, b1h);
        }
      }
    }
    __syncthreads();   // done reading stage st before it's refilled at kb+2
  }

  float hin = 0.5f * (float)h - 0.25f;
  int hi0 = hin < 0.f ? 0 : (int)hin;
  float hf = hin < 0.f ? 0.f : hin - (float)hi0;
  int hi1 = hi0 + 1 < 64 ? hi0 + 1 : 63;

#pragma unroll
  for (int mt = 0; mt < 2; mt++) {
#pragma unroll
    for (int half = 0; half < 2; half++) {
      int o = warpO + mt * 16 + lr + 8 * half;
      const float* xb = xh + (size_t)(b * 256 + o) * 4096;
      const float* r0 = xb + hi0 * 64;
      const float* r1 = xb + hi1 * 64;
      float* orow = out + (size_t)(b * 256 + o) * 16384 + h * 128;
#pragma unroll
      for (int nt = 0; nt < 8; nt++) {
        int w0 = wBase + nt * 8 + 2 * lc;
        float v[2];
#pragma unroll
        for (int j = 0; j < 2; j++) {
          int w = w0 + j;
          float win = 0.5f * (float)w - 0.25f;
          int wi0 = win < 0.f ? 0 : (int)win;
          float wf = win < 0.f ? 0.f : win - (float)wi0;
          int wi1 = wi0 + 1 < 64 ? wi0 + 1 : 63;
          float top = r0[wi0] * (1.f - wf) + r0[wi1] * wf;
          float bot = r1[wi0] * (1.f - wf) + r1[wi1] * wf;
          v[j] = acc[mt][nt][half * 2 + j] + top * (1.f - hf) + bot * hf;
        }
        *(float2*)&orow[w0] = make_float2(v[0], v[1]);
      }
    }
  }
}

// ---------------- launch ----------------
extern "C" void kernel_launch(void* const* d_in, const int* in_sizes, int n_in,
                              void* d_out, int out_size) {
  const float* x_high = (const float*)d_in[0];
  const float* x_low = (const float*)d_in[1];
  const float* w1 = (const float*)d_in[2];
  const float* b1 = (const float*)d_in[3];
  const float* w2 = (const float*)d_in[4];
  const float* b2 = (const float*)d_in[5];
  const float* refine_w = (const float*)d_in[6];
  float* out = (float*)d_out;

  const int SMEM_FFT = 2 * 128 * 129 * 4;                    // 132096 B
  const int SMEM_MIX = (4 * MIX_SA + 4 * MIX_SB) * 4;        // (16896+5632)*4 = 90112 B
  cudaFuncSetAttribute((const void*)fwd_fft_pair_kernel, cudaFuncAttributeMaxDynamicSharedMemorySize, SMEM_FFT);
  cudaFuncSetAttribute((const void*)inv_fft_pair_kernel, cudaFuncAttributeMaxDynamicSharedMemorySize, SMEM_FFT);
  cudaFuncSetAttribute((const void*)mix_kernel, cudaFuncAttributeMaxDynamicSharedMemorySize, SMEM_MIX);

  wsplit_kernel<<<128, 256>>>(refine_w);
  fwd_fft_pair_kernel<<<1024, 1024, SMEM_FFT>>>(x_low);
  mlp_kernel<<<8, 256>>>(w1, b1, w2, b2);
  cconv_kernel<<<dim3(1024, 8), 256>>>();
  bconv_kernel<<<dim3(1024, 7), 256>>>();
  inv_fft_pair_kernel<<<1024, 1024, SMEM_FFT>>>();
  mix_kernel<<<dim3(128, 2, 8), 256, SMEM_MIX>>>(x_high, out);
}

// round 16
// speedup vs baseline: 1.3737x; 1.0096x over previous
#include <cuda_runtime.h>
#include <cuda_bf16.h>
#include <math.h>
#include <stdint.h>

#ifndef M_PI
#define M_PI 3.14159265358979323846
#endif

#define FULLMASK 0xffffffffu

// ---------------- scratch (static device globals; no allocations) ----------------
__device__ float2   g_F[16777216];    // packed spectrum Z = fft2(x1 + i x2), shifted  [1024 pairs][16384]
__device__ float2   g_G[16777216];    // W = combined conv output (packed)             [1024 pairs][16384]
__device__ uint32_t g_Rhi[16777216];  // real(ifft2) bf16 hi, packed channel pairs [B*128][16384]
__device__ uint32_t g_Rlo[16777216];  // residual bf16 lo
__device__ float    g_kern[8 * 49];   // per-batch 7x7 kernel
__device__ uint32_t g_Whi[32768];     // refine_w split: [c2=128][o=256]
__device__ uint32_t g_Wlo[32768];     // residuals

// ---------------- complex helpers ----------------
__device__ __forceinline__ float2 cadd(float2 a, float2 b) { return make_float2(a.x + b.x, a.y + b.y); }
__device__ __forceinline__ float2 csub(float2 a, float2 b) { return make_float2(a.x - b.x, a.y - b.y); }
__device__ __forceinline__ float2 cmul(float2 a, float2 b) {
  return make_float2(a.x * b.x - a.y * b.y, a.x * b.y + a.y * b.x);
}

// ---------------- bf16 split helpers ----------------
__device__ __forceinline__ void split2_bf16(float xe, float xo, uint32_t& hi, uint32_t& lo) {
  __nv_bfloat16 he = __float2bfloat16_rn(xe);
  __nv_bfloat16 ho = __float2bfloat16_rn(xo);
  float re = xe - __bfloat162float(he);
  float ro = xo - __bfloat162float(ho);
  __nv_bfloat16 le = __float2bfloat16_rn(re);
  __nv_bfloat16 lo16 = __float2bfloat16_rn(ro);
  hi = (uint32_t)__bfloat16_as_ushort(he) | ((uint32_t)__bfloat16_as_ushort(ho) << 16);
  lo = (uint32_t)__bfloat16_as_ushort(le) | ((uint32_t)__bfloat16_as_ushort(lo16) << 16);
}

// ---------------- cp.async helpers ----------------
__device__ __forceinline__ void cp_async8(void* sptr, const void* gptr) {
  uint32_t sa = (uint32_t)__cvta_generic_to_shared(sptr);
  asm volatile("cp.async.ca.shared.global [%0], [%1], 8;" :: "r"(sa), "l"(gptr));
}
__device__ __forceinline__ void cp_commit() {
  asm volatile("cp.async.commit_group;" ::: "memory");
}
template <int N>
__device__ __forceinline__ void cp_wait_group() {
  asm volatile("cp.async.wait_group %0;" :: "n"(N) : "memory");
}

// ---------------- warp-resident 128-pt DIF FFT ----------------
template<int SGN>
__device__ __forceinline__ void make_twiddles(int lane, float2 tw[7]) {
  const float TP = 6.283185307179586f * (float)SGN;
  float fr[7] = { lane / 128.f, (lane + 32) / 128.f, lane / 64.f,
                  (lane & 15) / 32.f, (lane & 7) / 16.f, (lane & 3) / 8.f, (lane & 1) / 4.f };
#pragma unroll
  for (int i = 0; i < 7; i++) {
    float s, c;
    sincosf(TP * fr[i], &s, &c);
    tw[i] = make_float2(c, s);
  }
}

// Two INDEPENDENT 128-pt FFTs, stage-interleaved so the second chain's shuffles
// issue into the first chain's latency shadow (2-way ILP on the shfl chain).
__device__ __forceinline__ void fft128x2(float2 a[4], float2 b[4], const float2 tw[7], int lane) {
  float2 t, u;
  // stage half=64 (in-register: s <-> s+2)
  t = a[0]; u = a[2]; a[0] = cadd(t, u); a[2] = cmul(csub(t, u), tw[0]);
  t = b[0]; u = b[2]; b[0] = cadd(t, u); b[2] = cmul(csub(t, u), tw[0]);
  t = a[1]; u = a[3]; a[1] = cadd(t, u); a[3] = cmul(csub(t, u), tw[1]);
  t = b[1]; u = b[3]; b[1] = cadd(t, u); b[3] = cmul(csub(t, u), tw[1]);
  // stage half=32 (in-register: s <-> s+1)
  t = a[0]; u = a[1]; a[0] = cadd(t, u); a[1] = cmul(csub(t, u), tw[2]);
  t = b[0]; u = b[1]; b[0] = cadd(t, u); b[1] = cmul(csub(t, u), tw[2]);
  t = a[2]; u = a[3]; a[2] = cadd(t, u); a[3] = cmul(csub(t, u), tw[2]);
  t = b[2]; u = b[3]; b[2] = cadd(t, u); b[3] = cmul(csub(t, u), tw[2]);
  // stages half=16,8,4,2,1 via shfl_xor, both FFTs interleaved
#pragma unroll
  for (int hi = 0; hi < 5; hi++) {
    int h = 16 >> hi;
    bool up = (lane & h) != 0;
#pragma unroll
    for (int s = 0; s < 4; s++) {
      float pax = __shfl_xor_sync(FULLMASK, a[s].x, h);
      float pay = __shfl_xor_sync(FULLMASK, a[s].y, h);
      float pbx = __shfl_xor_sync(FULLMASK, b[s].x, h);
      float pby = __shfl_xor_sync(FULLMASK, b[s].y, h);
      float2 pa = make_float2(pax, pay);
      float2 pb = make_float2(pbx, pby);
      if (hi < 4) {
        a[s] = up ? cmul(csub(pa, a[s]), tw[3 + hi]) : cadd(a[s], pa);
        b[s] = up ? cmul(csub(pb, b[s]), tw[3 + hi]) : cadd(b[s], pb);
      } else {
        a[s] = up ? csub(pa, a[s]) : cadd(a[s], pa);
        b[s] = up ? csub(pb, b[s]) : cadd(b[s], pb);
      }
    }
  }
}

__device__ __forceinline__ int bitrev7(int p) { return (int)(__brev((unsigned)p) >> 25); }

// ---------------- forward FFT (channel-pair packed): x_low -> g_F (packed Z) ----------------
__global__ void __launch_bounds__(1024) fwd_fft_pair_kernel(const float* __restrict__ x) {
  extern __shared__ float sm[];
  float* sre = sm;
  float* sim = sm + 128 * 129;
  int pair = blockIdx.x;
  int ch1 = pair * 2, ch2 = ch1 + 1;
  int tid = threadIdx.x;
  int warp = tid >> 5, lane = tid & 31;
  float2 tw[7];
  make_twiddles<-1>(lane, tw);
  const float* x1 = x + (size_t)ch1 * 16384;
  const float* x2 = x + (size_t)ch2 * 16384;

  // row pass: two rows per iteration (rA, rA+64), interleaved FFTs
#pragma unroll
  for (int it = 0; it < 2; it++) {
    int rA = warp + it * 32;
    int rB = rA + 64;
    float2 va[4], vb[4];
#pragma unroll
    for (int s = 0; s < 4; s++) {
      int c = s * 32 + lane;
      va[s] = make_float2(x1[rA * 128 + c] * 0.0078125f, x2[rA * 128 + c] * 0.0078125f);
      vb[s] = make_float2(x1[rB * 128 + c] * 0.0078125f, x2[rB * 128 + c] * 0.0078125f);
    }
    fft128x2(va, vb, tw, lane);
#pragma unroll
    for (int s = 0; s < 4; s++) {
      int p = s * 32 + lane;
      int n = bitrev7(p) ^ 64;
      sre[rA * 129 + n] = va[s].x;
      sim[rA * 129 + n] = va[s].y;
      sre[rB * 129 + n] = vb[s].x;
      sim[rB * 129 + n] = vb[s].y;
    }
  }
  __syncthreads();
  // column pass (warp-private columns, in-place)
#pragma unroll
  for (int it = 0; it < 2; it++) {
    int cA = warp + it * 32;
    int cB = cA + 64;
    float2 va[4], vb[4];
#pragma unroll
    for (int s = 0; s < 4; s++) {
      int p = s * 32 + lane;
      va[s] = make_float2(sre[p * 129 + cA], sim[p * 129 + cA]);
      vb[s] = make_float2(sre[p * 129 + cB], sim[p * 129 + cB]);
    }
    fft128x2(va, vb, tw, lane);
#pragma unroll
    for (int s = 0; s < 4; s++) {
      int p = s * 32 + lane;
      int n = bitrev7(p) ^ 64;
      sre[n * 129 + cA] = va[s].x;
      sim[n * 129 + cA] = va[s].y;
      sre[n * 129 + cB] = vb[s].x;
      sim[n * 129 + cB] = vb[s].y;
    }
  }
  __syncthreads();
  float2* Zb = g_F + (size_t)pair * 16384;
  for (int i = tid; i < 16384; i += 1024) {
    int r = i >> 7, c = i & 127;
    Zb[i] = make_float2(sre[r * 129 + c], sim[r * 129 + c]);
  }
}

// ---------------- tiny path: center magnitudes (unpacked from Z) -> MLP -> kernel ----------------
__global__ void __launch_bounds__(256) mlp_kernel(const float* __restrict__ w1, const float* __restrict__ b1,
                                                  const float* __restrict__ w2, const float* __restrict__ b2) {
  int b = blockIdx.x;
  int t = threadIdx.x;
  __shared__ float part[49][4];
  __shared__ float flat[49];
  __shared__ float hbuf[32];
  __shared__ float prm[3];
  __shared__ float kv[49];
  __shared__ float ksum;

  if (t < 196) {
    int p = t >> 2, q = t & 3;
    int i = p / 7, j = p % 7;
    int im = 6 - i, jm = 6 - j;
    const float2* Zb = g_F + ((size_t)(b * 128 + q * 32)) * 16384;
    float s = 0.f;
#pragma unroll 4
    for (int pr = 0; pr < 32; pr++) {
      const float2* Zp = Zb + (size_t)pr * 16384;
      float2 z = Zp[(61 + i) * 128 + (61 + j)];
      float2 zm = Zp[(61 + im) * 128 + (61 + jm)];
      float e1 = z.x + zm.x, e2 = z.y - zm.y;
      float o1 = z.x - zm.x, o2 = z.y + zm.y;
      s += 0.5f * (sqrtf(e1 * e1 + e2 * e2) + sqrtf(o1 * o1 + o2 * o2));
    }
    part[p][q] = s;
  }
  __syncthreads();
  if (t < 49) flat[t] = (part[t][0] + part[t][1] + part[t][2] + part[t][3]) * (1.f / 256.f);
  __syncthreads();
  if (t < 32) {
    float a = b1[t];
#pragma unroll
    for (int i = 0; i < 49; i++) a += flat[i] * w1[t * 49 + i];
    hbuf[t] = fmaxf(a, 0.f);
  }
  __syncthreads();
  if (t < 3) {
    float a = b2[t];
#pragma unroll
    for (int u = 0; u < 32; u++) a += hbuf[u] * w2[t * 32 + u];
    prm[t] = a;
  }
  __syncthreads();
  if (t < 49) {
    float theta = atan2f(prm[0], prm[1]) * 0.5f + (float)M_PI * 0.5f;
    float lam1 = expf(prm[2]);
    float lam2 = 1.f / (lam1 + 1e-8f);
    float ct = cosf(theta), st = sinf(theta);
    int i = t / 7, j = t % 7;
    float yy = (float)(i - 3), xx = (float)(j - 3);
    float xr = xx * ct + yy * st;
    float yr = -xx * st + yy * ct;
    kv[t] = expf(-(xr * xr / (2.f * lam1 * lam1) + yr * yr / (2.f * lam2 * lam2)));
  }
  __syncthreads();
  if (t == 0) {
    float s = 0.f;
    for (int i = 0; i < 49; i++) s += kv[i];
    ksum = s;
  }
  __syncthreads();
  if (t < 49) g_kern[b * 49 + t] = kv[t] / (ksum + 1e-8f);
}

// ---------------- circular conv (interior-exact): Z -> W, no boundary logic at all ----------------
__global__ void __launch_bounds__(256) cconv_kernel() {
  __shared__ float2 tile[22][134];
  __shared__ float kc[49];
  int pair = blockIdx.x;          // 0..1023
  int b = pair >> 7;
  int rBase = blockIdx.y * 16;
  int tid = threadIdx.x;
  if (tid < 49) kc[tid] = g_kern[b * 49 + tid];
  const float2* Zb = g_F + (size_t)pair * 16384;
  for (int idx = tid; idx < 22 * 134; idx += 256) {
    int tr = idx / 134, tc = idx % 134;
    int gr = (rBase - 3 + tr) & 127;   // circular halo
    int gc = (tc - 3) & 127;
    tile[tr][tc] = Zb[gr * 128 + gc];
  }
  __syncthreads();
  int w = tid & 127, rg = tid >> 7;
  float2* Wb = g_G + (size_t)pair * 16384;
#pragma unroll
  for (int rr = 0; rr < 8; rr++) {
    int rl = rg * 8 + rr;
    float sre = 0.f, simv = 0.f;
#pragma unroll
    for (int dy = 0; dy < 7; dy++)
#pragma unroll
      for (int dx = 0; dx < 7; dx++) {
        float2 in = tile[rl + dy][w + dx];
        float k = kc[dy * 7 + dx];
        sre += in.x * k;
        simv += in.y * k;
      }
    Wb[(rBase + rl) * 128 + w] = make_float2(sre, simv);
  }
}

// ---------------- boundary fixup: 1743-pixel frame with exact pad/mirror weights ----------------
// grid (1024 pairs, 7 slices) — one 256-px slice per block for latency hiding.
__global__ void __launch_bounds__(256) bconv_kernel() {
  __shared__ float kc[49];
  int pair = blockIdx.x;          // 0..1023
  int b = pair >> 7;
  int tid = threadIdx.x;
  if (tid < 49) kc[tid] = g_kern[b * 49 + tid];
  __syncthreads();
  const float2* Zb = g_F + (size_t)pair * 16384;
  float2* Wb = g_G + (size_t)pair * 16384;
  int idx = blockIdx.y * 256 + tid;
  if (idx < 1743) {
    int n1, n2;
    if (idx < 896) {
      int r = idx >> 7;
      n1 = (r < 4) ? r : (121 + r);     // 0..3, 125..127
      n2 = idx & 127;
    } else {
      int j = idx - 896;
      n1 = 4 + j / 7;                   // 4..124
      int c = j % 7;
      n2 = (c < 4) ? c : (121 + c);     // 0..3, 125..127
    }
    float wy[7], wz[7], vy[7], vz[7];   // per-axis a/b indicators
#pragma unroll
    for (int d = 0; d < 7; d++) {
      int dd = d - 3;
      int j1 = n1 + dd, j2 = n2 + dd;
      wy[d] = (j1 >= 0 && j1 <= 127) ? 1.f : 0.f;
      vy[d] = ((n1 >= 1) ? (j1 >= 1 && j1 <= 128) : (dd <= 0)) ? 1.f : 0.f;
      wz[d] = (j2 >= 0 && j2 <= 127) ? 1.f : 0.f;
      vz[d] = ((n2 >= 1) ? (j2 >= 1 && j2 <= 128) : (dd <= 0)) ? 1.f : 0.f;
    }
    float sre = 0.f, simv = 0.f;
#pragma unroll
    for (int dy = 0; dy < 7; dy++) {
      int r = (n1 + dy - 3) & 127;
      const float2* Zr = Zb + r * 128;
#pragma unroll
      for (int dx = 0; dx < 7; dx++) {
        float wt = 0.5f * (wy[dy] * wz[dx] + vy[dy] * vz[dx]) * kc[dy * 7 + dx];
        float2 in = Zr[(n2 + dx - 3) & 127];
        sre += in.x * wt;
        simv += in.y * wt;
      }
    }
    Wb[n1 * 128 + n2] = make_float2(sre, simv);
  }
}

// ---------------- inverse FFT: W -> g_Rhi/g_Rlo (bf16 split) ----------------
__global__ void __launch_bounds__(1024) inv_fft_pair_kernel() {
  extern __shared__ float sm[];
  float* sre = sm;
  float* sim = sm + 128 * 129;
  int pair = blockIdx.x;
  int tid = threadIdx.x;
  int warp = tid >> 5, lane = tid & 31;
  float2 tw[7];
  make_twiddles<1>(lane, tw);
  const float2* Wb = g_G + (size_t)pair * 16384;

#pragma unroll
  for (int it = 0; it < 2; it++) {
    int rA = warp + it * 32;
    int rB = rA + 64;
    float2 va[4], vb[4];
#pragma unroll
    for (int s = 0; s < 4; s++) {
      int cidx = (s * 32 + lane) ^ 64;      // ifftshift on cols
      float2 ga = Wb[rA * 128 + cidx];
      float2 gb = Wb[rB * 128 + cidx];
      va[s] = make_float2(ga.x * 0.0078125f, ga.y * 0.0078125f);
      vb[s] = make_float2(gb.x * 0.0078125f, gb.y * 0.0078125f);
    }
    fft128x2(va, vb, tw, lane);
#pragma unroll
    for (int s = 0; s < 4; s++) {
      int p = s * 32 + lane;
      int n = bitrev7(p);
      sre[rA * 129 + n] = va[s].x;
      sim[rA * 129 + n] = va[s].y;
      sre[rB * 129 + n] = vb[s].x;
      sim[rB * 129 + n] = vb[s].y;
    }
  }
  __syncthreads();
#pragma unroll
  for (int it = 0; it < 2; it++) {
    int cA = warp + it * 32;
    int cB = cA + 64;
    float2 va[4], vb[4];
#pragma unroll
    for (int s = 0; s < 4; s++) {
      int ridx = (s * 32 + lane) ^ 64;      // ifftshift on rows
      va[s] = make_float2(sre[ridx * 129 + cA], sim[ridx * 129 + cA]);
      vb[s] = make_float2(sre[ridx * 129 + cB], sim[ridx * 129 + cB]);
    }
    fft128x2(va, vb, tw, lane);
#pragma unroll
    for (int s = 0; s < 4; s++) {
      int p = s * 32 + lane;
      int n = bitrev7(p);
      sre[n * 129 + cA] = va[s].x;
      sim[n * 129 + cA] = va[s].y;
      sre[n * 129 + cB] = vb[s].x;
      sim[n * 129 + cB] = vb[s].y;
    }
  }
  __syncthreads();
  uint32_t* Rh = g_Rhi + (size_t)pair * 16384;
  uint32_t* Rl = g_Rlo + (size_t)pair * 16384;
  for (int i = tid; i < 16384; i += 1024) {
    int r = i >> 7, c = i & 127;
    uint32_t hi, lo;
    split2_bf16(sre[r * 129 + c], sim[r * 129 + c], hi, lo);
    Rh[i] = hi;
    Rl[i] = lo;
  }
}

// ---------------- weight prep: refine_w -> bf16-split packed channel pairs ----------------
__global__ void __launch_bounds__(256) wsplit_kernel(const float* __restrict__ W) {
  int idx = blockIdx.x * 256 + threadIdx.x;   // 0..32767
  int c2 = idx & 127, o = idx >> 7;
  float xe = W[o * 256 + 2 * c2];
  float xo = W[o * 256 + 2 * c2 + 1];
  uint32_t hi, lo;
  split2_bf16(xe, xo, hi, lo);
  g_Whi[c2 * 256 + o] = hi;
  g_Wlo[c2 * 256 + o] = lo;
}

// ---------------- bf16 MMA helper ----------------
__device__ __forceinline__ void mma_bf16(float* c, uint32_t a0, uint32_t a1, uint32_t a2, uint32_t a3,
                                         uint32_t b0, uint32_t b1) {
  asm volatile(
      "mma.sync.aligned.m16n8k16.row.col.f32.bf16.bf16.f32 "
      "{%0,%1,%2,%3}, {%4,%5,%6,%7}, {%8,%9}, {%0,%1,%2,%3};"
      : "+f"(c[0]), "+f"(c[1]), "+f"(c[2]), "+f"(c[3])
      : "r"(a0), "r"(a1), "r"(a2), "r"(a3), "r"(b0), "r"(b1));
}

// ---------------- channel mix GEMM (3-term bf16, cp.async double-buffered) + bilinear epilogue ----------------
#define MIX_SA 4224   // 16*264 per stage
#define MIX_SB 1408   // 16*88  per stage
__global__ void __launch_bounds__(256, 2) mix_kernel(const float* __restrict__ xh, float* __restrict__ out) {
  extern __shared__ uint32_t smx[];
  uint32_t* AsHi = smx;                 // [2][16][264]
  uint32_t* AsLo = smx + 2 * MIX_SA;    // [2][16][264]
  uint32_t* BsHi = smx + 4 * MIX_SA;    // [2][16][88]
  uint32_t* BsLo = smx + 4 * MIX_SA + 2 * MIX_SB;

  int b = blockIdx.z;
  int h = blockIdx.x;
  int wBase = blockIdx.y * 64;
  int tid = threadIdx.x;
  int warp = tid >> 5, lane = tid & 31;
  int lr = lane >> 2, lc = lane & 3;
  int warpO = warp * 32;

  float acc[2][8][4];
#pragma unroll
  for (int mt = 0; mt < 2; mt++)
#pragma unroll
    for (int nt = 0; nt < 8; nt++)
#pragma unroll
      for (int q = 0; q < 4; q++) acc[mt][nt][q] = 0.f;

  const uint32_t* RhB = g_Rhi + (size_t)b * 128 * 16384 + h * 128 + wBase;
  const uint32_t* RlB = g_Rlo + (size_t)b * 128 * 16384 + h * 128 + wBase;

  auto load_stage = [&](int st, int kb) {
#pragma unroll
    for (int it = 0; it < 8; it++) {        // A: 16 k2 x 128 o2 (8B each)
      int item = it * 256 + tid;
      int o2 = item & 127;
      int k2 = item >> 7;
      cp_async8(&AsHi[st * MIX_SA + k2 * 264 + o2 * 2], &g_Whi[(kb * 16 + k2) * 256 + o2 * 2]);
      cp_async8(&AsLo[st * MIX_SA + k2 * 264 + o2 * 2], &g_Wlo[(kb * 16 + k2) * 256 + o2 * 2]);
    }
#pragma unroll
    for (int it = 0; it < 2; it++) {        // B: 16 k2 x 32 w2 (8B each)
      int item = it * 256 + tid;
      int w2 = item & 31;
      int k2 = item >> 5;
      cp_async8(&BsHi[st * MIX_SB + k2 * 88 + w2 * 2], &RhB[(size_t)(kb * 16 + k2) * 16384 + w2 * 2]);
      cp_async8(&BsLo[st * MIX_SB + k2 * 88 + w2 * 2], &RlB[(size_t)(kb * 16 + k2) * 16384 + w2 * 2]);
    }
    cp_commit();
  };

  load_stage(0, 0);
  for (int kb = 0; kb < 8; kb++) {
    int st = kb & 1;
    if (kb + 1 < 8) {
      load_stage(1 - st, kb + 1);
      cp_wait_group<1>();
    } else {
      cp_wait_group<0>();
    }
    __syncthreads();
    const uint32_t* aH = AsHi + st * MIX_SA;
    const uint32_t* aL = AsLo + st * MIX_SA;
    const uint32_t* bH = BsHi + st * MIX_SB;
    const uint32_t* bL = BsLo + st * MIX_SB;
#pragma unroll
    for (int s = 0; s < 2; s++) {
      uint32_t ahi[2][4], alo[2][4];
#pragma unroll
      for (int mt = 0; mt < 2; mt++) {
#pragma unroll
        for (int rg = 0; rg < 4; rg++) {
          int k2 = s * 8 + lc + 4 * (rg >> 1);
          int o = warpO + mt * 16 + lr + 8 * (rg & 1);
          ahi[mt][rg] = aH[k2 * 264 + o];
          alo[mt][rg] = aL[k2 * 264 + o];
        }
      }
      int kr0 = (s * 8 + lc) * 88 + lr;
      int kr1 = (s * 8 + lc + 4) * 88 + lr;
#pragma unroll
      for (int nt = 0; nt < 8; nt++) {
        uint32_t b0h = bH[kr0 + nt * 8];
        uint32_t b1h = bH[kr1 + nt * 8];
        uint32_t b0l = bL[kr0 + nt * 8];
        uint32_t b1l = bL[kr1 + nt * 8];
#pragma unroll
        for (int mt = 0; mt < 2; mt++) {
          mma_bf16(acc[mt][nt], ahi[mt][0], ahi[mt][1], ahi[mt][2], ahi[mt][3], b0h, b1h);
          mma_bf16(acc[mt][nt], ahi[mt][0], ahi[mt][1], ahi[mt][2], ahi[mt][3], b0l, b1l);
          mma_bf16(acc[mt][nt], alo[mt][0], alo[mt][1], alo[mt][2], alo[mt][3], b0h, b1h);
        }
      }
    }
    __syncthreads();
  }

  float hin = 0.5f * (float)h - 0.25f;
  int hi0 = hin < 0.f ? 0 : (int)hin;
  float hf = hin < 0.f ? 0.f : hin - (float)hi0;
  int hi1 = hi0 + 1 < 64 ? hi0 + 1 : 63;

#pragma unroll
  for (int mt = 0; mt < 2; mt++) {
#pragma unroll
    for (int half = 0; half < 2; half++) {
      int o = warpO + mt * 16 + lr + 8 * half;
      const float* xb = xh + (size_t)(b * 256 + o) * 4096;
      const float* r0 = xb + hi0 * 64;
      const float* r1 = xb + hi1 * 64;
      float* orow = out + (size_t)(b * 256 + o) * 16384 + h * 128;
#pragma unroll
      for (int nt = 0; nt < 8; nt++) {
        int w0 = wBase + nt * 8 + 2 * lc;
        float v[2];
#pragma unroll
        for (int j = 0; j < 2; j++) {
          int w = w0 + j;
          float win = 0.5f * (float)w - 0.25f;
          int wi0 = win < 0.f ? 0 : (int)win;
          float wf = win < 0.f ? 0.f : win - (float)wi0;
          int wi1 = wi0 + 1 < 64 ? wi0 + 1 : 63;
          float top = r0[wi0] * (1.f - wf) + r0[wi1] * wf;
          float bot = r1[wi0] * (1.f - wf) + r1[wi1] * wf;
          v[j] = acc[mt][nt][half * 2 + j] + top * (1.f - hf) + bot * hf;
        }
        *(float2*)&orow[w0] = make_float2(v[0], v[1]);
      }
    }
  }
}

// ---------------- launch ----------------
extern "C" void kernel_launch(void* const* d_in, const int* in_sizes, int n_in,
                              void* d_out, int out_size) {
  const float* x_high = (const float*)d_in[0];
  const float* x_low = (const float*)d_in[1];
  const float* w1 = (const float*)d_in[2];
  const float* b1 = (const float*)d_in[3];
  const float* w2 = (const float*)d_in[4];
  const float* b2 = (const float*)d_in[5];
  const float* refine_w = (const float*)d_in[6];
  float* out = (float*)d_out;

  const int SMEM_FFT = 2 * 128 * 129 * 4;                    // 132096 B
  const int SMEM_MIX = (4 * MIX_SA + 4 * MIX_SB) * 4;        // 90112 B
  cudaFuncSetAttribute((const void*)fwd_fft_pair_kernel, cudaFuncAttributeMaxDynamicSharedMemorySize, SMEM_FFT);
  cudaFuncSetAttribute((const void*)inv_fft_pair_kernel, cudaFuncAttributeMaxDynamicSharedMemorySize, SMEM_FFT);
  cudaFuncSetAttribute((const void*)mix_kernel, cudaFuncAttributeMaxDynamicSharedMemorySize, SMEM_MIX);

  wsplit_kernel<<<128, 256>>>(refine_w);
  fwd_fft_pair_kernel<<<1024, 1024, SMEM_FFT>>>(x_low);
  mlp_kernel<<<8, 256>>>(w1, b1, w2, b2);
  cconv_kernel<<<dim3(1024, 8), 256>>>();
  bconv_kernel<<<dim3(1024, 7), 256>>>();
  inv_fft_pair_kernel<<<1024, 1024, SMEM_FFT>>>();
  mix_kernel<<<dim3(128, 2, 8), 256, SMEM_MIX>>>(x_high, out);
}

// round 17
// speedup vs baseline: 1.5547x; 1.1317x over previous
#include <cuda_runtime.h>
#include <cuda_bf16.h>
#include <math.h>
#include <stdint.h>

#ifndef M_PI
#define M_PI 3.14159265358979323846
#endif

#define FULLMASK 0xffffffffu

// ---------------- scratch (static device globals; no allocations) ----------------
// g_Fb per pair (stride 3392 float2): [0,1664) rows band {0..6,122..127}x128,
// [1664,3328) cols band 128x{0..6,122..127} (layout [r][ci]), [3328,3377) center 7x7.
__device__ float2   g_Fb[3473408];    // 1024 pairs * 3392
__device__ uint32_t g_Rhi[16777216];  // real(ifft2) bf16 hi, packed channel pairs [1024 pairs][16384]
__device__ uint32_t g_Rlo[16777216];  // residual bf16 lo
__device__ float    g_kern[8 * 49];   // per-batch 7x7 kernel
__device__ uint32_t g_Whi[32768];     // refine_w split: [c2=128][o=256]
__device__ uint32_t g_Wlo[32768];     // residuals

// ---------------- complex helpers ----------------
__device__ __forceinline__ float2 cadd(float2 a, float2 b) { return make_float2(a.x + b.x, a.y + b.y); }
__device__ __forceinline__ float2 csub(float2 a, float2 b) { return make_float2(a.x - b.x, a.y - b.y); }
__device__ __forceinline__ float2 cmul(float2 a, float2 b) {
  return make_float2(a.x * b.x - a.y * b.y, a.x * b.y + a.y * b.x);
}

// ---------------- bf16 split helpers ----------------
__device__ __forceinline__ void split2_bf16(float xe, float xo, uint32_t& hi, uint32_t& lo) {
  __nv_bfloat16 he = __float2bfloat16_rn(xe);
  __nv_bfloat16 ho = __float2bfloat16_rn(xo);
  float re = xe - __bfloat162float(he);
  float ro = xo - __bfloat162float(ho);
  __nv_bfloat16 le = __float2bfloat16_rn(re);
  __nv_bfloat16 lo16 = __float2bfloat16_rn(ro);
  hi = (uint32_t)__bfloat16_as_ushort(he) | ((uint32_t)__bfloat16_as_ushort(ho) << 16);
  lo = (uint32_t)__bfloat16_as_ushort(le) | ((uint32_t)__bfloat16_as_ushort(lo16) << 16);
}

// ---------------- cp.async helpers ----------------
__device__ __forceinline__ void cp_async8(void* sptr, const void* gptr) {
  uint32_t sa = (uint32_t)__cvta_generic_to_shared(sptr);
  asm volatile("cp.async.ca.shared.global [%0], [%1], 8;" :: "r"(sa), "l"(gptr));
}
__device__ __forceinline__ void cp_commit() {
  asm volatile("cp.async.commit_group;" ::: "memory");
}
template <int N>
__device__ __forceinline__ void cp_wait_group() {
  asm volatile("cp.async.wait_group %0;" :: "n"(N) : "memory");
}

// ---------------- warp-resident 128-pt DIF FFT ----------------
template<int SGN>
__device__ __forceinline__ void make_twiddles(int lane, float2 tw[7]) {
  const float TP = 6.283185307179586f * (float)SGN;
  float fr[7] = { lane / 128.f, (lane + 32) / 128.f, lane / 64.f,
                  (lane & 15) / 32.f, (lane & 7) / 16.f, (lane & 3) / 8.f, (lane & 1) / 4.f };
#pragma unroll
  for (int i = 0; i < 7; i++) {
    float s, c;
    sincosf(TP * fr[i], &s, &c);
    tw[i] = make_float2(c, s);
  }
}

__device__ __forceinline__ void fft128(float2 v[4], const float2 tw[7], int lane) {
  float2 t, u;
  t = v[0]; u = v[2]; v[0] = cadd(t, u); v[2] = cmul(csub(t, u), tw[0]);
  t = v[1]; u = v[3]; v[1] = cadd(t, u); v[3] = cmul(csub(t, u), tw[1]);
  t = v[0]; u = v[1]; v[0] = cadd(t, u); v[1] = cmul(csub(t, u), tw[2]);
  t = v[2]; u = v[3]; v[2] = cadd(t, u); v[3] = cmul(csub(t, u), tw[2]);
#pragma unroll
  for (int hi = 0; hi < 5; hi++) {
    int h = 16 >> hi;
    bool up = (lane & h) != 0;
#pragma unroll
    for (int s = 0; s < 4; s++) {
      float prx = __shfl_xor_sync(FULLMASK, v[s].x, h);
      float pry = __shfl_xor_sync(FULLMASK, v[s].y, h);
      float2 pr = make_float2(prx, pry);
      if (hi < 4) {
        v[s] = up ? cmul(csub(pr, v[s]), tw[3 + hi]) : cadd(v[s], pr);
      } else {
        v[s] = up ? csub(pr, v[s]) : cadd(v[s], pr);
      }
    }
  }
}

// Two independent FFTs interleaved (kept for fwd)
__device__ __forceinline__ void fft128x2(float2 a[4], float2 b[4], const float2 tw[7], int lane) {
  float2 t, u;
  t = a[0]; u = a[2]; a[0] = cadd(t, u); a[2] = cmul(csub(t, u), tw[0]);
  t = b[0]; u = b[2]; b[0] = cadd(t, u); b[2] = cmul(csub(t, u), tw[0]);
  t = a[1]; u = a[3]; a[1] = cadd(t, u); a[3] = cmul(csub(t, u), tw[1]);
  t = b[1]; u = b[3]; b[1] = cadd(t, u); b[3] = cmul(csub(t, u), tw[1]);
  t = a[0]; u = a[1]; a[0] = cadd(t, u); a[1] = cmul(csub(t, u), tw[2]);
  t = b[0]; u = b[1]; b[0] = cadd(t, u); b[1] = cmul(csub(t, u), tw[2]);
  t = a[2]; u = a[3]; a[2] = cadd(t, u); a[3] = cmul(csub(t, u), tw[2]);
  t = b[2]; u = b[3]; b[2] = cadd(t, u); b[3] = cmul(csub(t, u), tw[2]);
#pragma unroll
  for (int hi = 0; hi < 5; hi++) {
    int h = 16 >> hi;
    bool up = (lane & h) != 0;
#pragma unroll
    for (int s = 0; s < 4; s++) {
      float pax = __shfl_xor_sync(FULLMASK, a[s].x, h);
      float pay = __shfl_xor_sync(FULLMASK, a[s].y, h);
      float pbx = __shfl_xor_sync(FULLMASK, b[s].x, h);
      float pby = __shfl_xor_sync(FULLMASK, b[s].y, h);
      float2 pa = make_float2(pax, pay);
      float2 pb = make_float2(pbx, pby);
      if (hi < 4) {
        a[s] = up ? cmul(csub(pa, a[s]), tw[3 + hi]) : cadd(a[s], pa);
        b[s] = up ? cmul(csub(pb, b[s]), tw[3 + hi]) : cadd(b[s], pb);
      } else {
        a[s] = up ? csub(pa, a[s]) : cadd(a[s], pa);
        b[s] = up ? csub(pb, b[s]) : cadd(b[s], pb);
      }
    }
  }
}

__device__ __forceinline__ int bitrev7(int p) { return (int)(__brev((unsigned)p) >> 25); }

// ---------------- forward FFT (channel-pair packed): x_low -> g_Fb (bands + center only) ----------------
__global__ void __launch_bounds__(1024) fwd_fft_pair_kernel(const float* __restrict__ x) {
  extern __shared__ float sm[];
  float* sre = sm;
  float* sim = sm + 128 * 129;
  int pair = blockIdx.x;
  int ch1 = pair * 2, ch2 = ch1 + 1;
  int tid = threadIdx.x;
  int warp = tid >> 5, lane = tid & 31;
  float2 tw[7];
  make_twiddles<-1>(lane, tw);
  const float* x1 = x + (size_t)ch1 * 16384;
  const float* x2 = x + (size_t)ch2 * 16384;

#pragma unroll
  for (int it = 0; it < 2; it++) {
    int rA = warp + it * 32;
    int rB = rA + 64;
    float2 va[4], vb[4];
#pragma unroll
    for (int s = 0; s < 4; s++) {
      int c = s * 32 + lane;
      va[s] = make_float2(x1[rA * 128 + c] * 0.0078125f, x2[rA * 128 + c] * 0.0078125f);
      vb[s] = make_float2(x1[rB * 128 + c] * 0.0078125f, x2[rB * 128 + c] * 0.0078125f);
    }
    fft128x2(va, vb, tw, lane);
#pragma unroll
    for (int s = 0; s < 4; s++) {
      int p = s * 32 + lane;
      int n = bitrev7(p) ^ 64;
      sre[rA * 129 + n] = va[s].x;
      sim[rA * 129 + n] = va[s].y;
      sre[rB * 129 + n] = vb[s].x;
      sim[rB * 129 + n] = vb[s].y;
    }
  }
  __syncthreads();
#pragma unroll
  for (int it = 0; it < 2; it++) {
    int cA = warp + it * 32;
    int cB = cA + 64;
    float2 va[4], vb[4];
#pragma unroll
    for (int s = 0; s < 4; s++) {
      int p = s * 32 + lane;
      va[s] = make_float2(sre[p * 129 + cA], sim[p * 129 + cA]);
      vb[s] = make_float2(sre[p * 129 + cB], sim[p * 129 + cB]);
    }
    fft128x2(va, vb, tw, lane);
#pragma unroll
    for (int s = 0; s < 4; s++) {
      int p = s * 32 + lane;
      int n = bitrev7(p) ^ 64;
      sre[n * 129 + cA] = va[s].x;
      sim[n * 129 + cA] = va[s].y;
      sre[n * 129 + cB] = vb[s].x;
      sim[n * 129 + cB] = vb[s].y;
    }
  }
  __syncthreads();
  // write only bands + center
  float2* Fb = g_Fb + (size_t)pair * 3392;
  for (int i = tid; i < 3377; i += 1024) {
    int r, c;
    if (i < 1664) {
      int ri = i >> 7; c = i & 127;
      r = (ri < 7) ? ri : (115 + ri);
    } else if (i < 3328) {
      int ii = i - 1664;
      r = ii / 13;
      int ci = ii - r * 13;
      c = (ci < 7) ? ci : (115 + ci);
    } else {
      int ii = i - 3328;
      r = 61 + ii / 7;
      c = 61 + ii % 7;
    }
    Fb[i] = make_float2(sre[r * 129 + c], sim[r * 129 + c]);
  }
}

// ---------------- tiny path: center magnitudes -> MLP -> anisotropic kernel ----------------
__global__ void __launch_bounds__(256) mlp_kernel(const float* __restrict__ w1, const float* __restrict__ b1,
                                                  const float* __restrict__ w2, const float* __restrict__ b2) {
  int b = blockIdx.x;
  int t = threadIdx.x;
  __shared__ float part[49][4];
  __shared__ float flat[49];
  __shared__ float hbuf[32];
  __shared__ float prm[3];
  __shared__ float kv[49];
  __shared__ float ksum;

  if (t < 196) {
    int p = t >> 2, q = t & 3;
    int i = p / 7, j = p % 7;
    int im = 6 - i, jm = 6 - j;
    const float2* Cb = g_Fb + ((size_t)(b * 128 + q * 32)) * 3392 + 3328;
    float s = 0.f;
#pragma unroll 4
    for (int pr = 0; pr < 32; pr++) {
      const float2* Zp = Cb + (size_t)pr * 3392;
      float2 z = Zp[i * 7 + j];
      float2 zm = Zp[im * 7 + jm];
      float e1 = z.x + zm.x, e2 = z.y - zm.y;
      float o1 = z.x - zm.x, o2 = z.y + zm.y;
      s += 0.5f * (sqrtf(e1 * e1 + e2 * e2) + sqrtf(o1 * o1 + o2 * o2));
    }
    part[p][q] = s;
  }
  __syncthreads();
  if (t < 49) flat[t] = (part[t][0] + part[t][1] + part[t][2] + part[t][3]) * (1.f / 256.f);
  __syncthreads();
  if (t < 32) {
    float a = b1[t];
#pragma unroll
    for (int i = 0; i < 49; i++) a += flat[i] * w1[t * 49 + i];
    hbuf[t] = fmaxf(a, 0.f);
  }
  __syncthreads();
  if (t < 3) {
    float a = b2[t];
#pragma unroll
    for (int u = 0; u < 32; u++) a += hbuf[u] * w2[t * 32 + u];
    prm[t] = a;
  }
  __syncthreads();
  if (t < 49) {
    float theta = atan2f(prm[0], prm[1]) * 0.5f + (float)M_PI * 0.5f;
    float lam1 = expf(prm[2]);
    float lam2 = 1.f / (lam1 + 1e-8f);
    float ct = cosf(theta), st = sinf(theta);
    int i = t / 7, j = t % 7;
    float yy = (float)(i - 3), xx = (float)(j - 3);
    float xr = xx * ct + yy * st;
    float yr = -xx * st + yy * ct;
    kv[t] = expf(-(xr * xr / (2.f * lam1 * lam1) + yr * yr / (2.f * lam2 * lam2)));
  }
  __syncthreads();
  if (t == 0) {
    float s = 0.f;
    for (int i = 0; i < 49; i++) s += kv[i];
    ksum = s;
  }
  __syncthreads();
  if (t < 49) g_kern[b * 49 + t] = kv[t] / (ksum + 1e-8f);
}

// ---------------- final: conv-theorem main term + sparse frame-delta IFFT + bf16 split ----------------
// out(m) = z(m)*K(m) + (1/128)[(-1)^m1 Σ_j cs[m1][j]*P_j(m2) + (-1)^m2 Σ_j cs[m2][j]*Q_j(m1)]
// P_j = IFFT of Δs row 61+j;  Q_j = IFFT of Δs col 61+j (rows 61..67 excluded).
// K(m) = Σ_dy cs[m1][dy].x*KC[dy][m2] - cs[m1][dy].y*KS[dy][m2].
__global__ void __launch_bounds__(1024) final_kernel(const float* __restrict__ x) {
  extern __shared__ float smf[];
  float2* band = (float2*)smf;       // [3328]: rowsB [ri*128+c] then colsB [r*13+ci]
  float2* DP = band + 3328;          // [7*128]  Drow -> (in-place) Prow [j*128 + m2]
  float2* Dc = DP + 896;             // [128*7]  Dcol [n~1*7 + j]
  float2* Qc = Dc + 896;             // [7*128]  Qcol [j*128 + m1]
  float2* cs = Qc + 896;             // [128*7]  e^{2pi i m (d-3)/128}
  float* KC = (float*)(cs + 896);    // [7*128]
  float* KS = KC + 896;              // [7*128]
  __shared__ float kc[49];

  int pair = blockIdx.x, bb = pair >> 7;
  int tid = threadIdx.x, warp = tid >> 5, lane = tid & 31;
  if (tid < 49) kc[tid] = g_kern[bb * 49 + tid];
  const float2* Fb = g_Fb + (size_t)pair * 3392;
  for (int i = tid; i < 3328; i += 1024) band[i] = Fb[i];
  if (tid < 896) {
    int m = tid / 7, d = tid - m * 7;
    float ang = (float)(m * (d - 3)) * 0.04908738521234052f;  // pi/64
    float sv, cv;
    sincosf(ang, &sv, &cv);
    cs[tid] = make_float2(cv, sv);
  }
  __syncthreads();

  // KC/KS tables
  if (tid < 896) {
    int dy = tid >> 7, m2 = tid & 127;
    float ac = 0.f, as = 0.f;
#pragma unroll
    for (int dx = 0; dx < 7; dx++) {
      float kk = kc[dy * 7 + dx];
      float2 e = cs[m2 * 7 + dx];
      ac += kk * e.x;
      as += kk * e.y;
    }
    KC[tid] = ac;
    KS[tid] = as;
  }

  // frame delta (Δ = W_exact - W_circ), in ifftshifted coordinates
  for (int item = tid; item < 1792; item += 1024) {
    if (item < 896) {
      // Drow: n~1 = 61+j (full width)
      int j = item >> 7, t2 = item & 127;
      int n1 = (125 + j) & 127;
      int n2 = (t2 + 64) & 127;
      float ax = 0.f, ay = 0.f;
      for (int dy = 0; dy < 7; dy++) {
        int dd1 = dy - 3, j1 = n1 + dd1;
        int r = (n1 + dd1) & 127;
        int ri = (r <= 6) ? r : (r - 115);
        float a1 = (j1 >= 0 && j1 <= 127) ? 1.f : 0.f;
        float b1 = ((n1 >= 1) ? (j1 >= 1 && j1 <= 128) : (dd1 <= 0)) ? 1.f : 0.f;
        const float2* rb = band + ri * 128;
        for (int dx = 0; dx < 7; dx++) {
          int dd2 = dx - 3, j2 = n2 + dd2;
          float a2 = (j2 >= 0 && j2 <= 127) ? 1.f : 0.f;
          float b2v = ((n2 >= 1) ? (j2 >= 1 && j2 <= 128) : (dd2 <= 0)) ? 1.f : 0.f;
          float kk = (0.5f * (a1 * a2 + b1 * b2v) - 1.f) * kc[dy * 7 + dx];
          float2 v = rb[(n2 + dd2) & 127];
          ax += v.x * kk;
          ay += v.y * kk;
        }
      }
      DP[j * 128 + t2] = make_float2(ax, ay);
    } else {
      // Dcol: n~2 = 61+j, rows outside 61..67
      int i2 = item - 896;
      int t1 = i2 / 7, j = i2 - t1 * 7;
      if (t1 >= 61 && t1 <= 67) {
        Dc[t1 * 7 + j] = make_float2(0.f, 0.f);
      } else {
        int n1 = (t1 + 64) & 127;     // in [4,124] -> row indicators all 1
        int n2 = (125 + j) & 127;
        float wv[7];
#pragma unroll
        for (int dx = 0; dx < 7; dx++) {
          int dd2 = dx - 3, j2 = n2 + dd2;
          float a2 = (j2 >= 0 && j2 <= 127) ? 1.f : 0.f;
          float b2v = ((n2 >= 1) ? (j2 >= 1 && j2 <= 128) : (dd2 <= 0)) ? 1.f : 0.f;
          wv[dx] = 0.5f * (a2 + b2v) - 1.f;
        }
        const float2* cb = band + 1664;
        float ax = 0.f, ay = 0.f;
        for (int dy = 0; dy < 7; dy++) {
          int r = n1 + dy - 3;        // in [1,127], no wrap
          for (int dx = 0; dx < 7; dx++) {
            int cph = (n2 + dx - 3) & 127;
            int ci = (cph <= 6) ? cph : (cph - 115);
            float kk = wv[dx] * kc[dy * 7 + dx];
            float2 v = cb[r * 13 + ci];
            ax += v.x * kk;
            ay += v.y * kk;
          }
        }
        Dc[t1 * 7 + j] = make_float2(ax, ay);
      }
    }
  }
  __syncthreads();

  // 14 sparse-axis IFFTs
  if (warp < 14) {
    float2 twd[7];
    make_twiddles<1>(lane, twd);
    if (warp < 7) {
      float2 v[4];
#pragma unroll
      for (int s = 0; s < 4; s++) v[s] = DP[warp * 128 + s * 32 + lane];
      fft128(v, twd, lane);
#pragma unroll
      for (int s = 0; s < 4; s++) {
        int p = s * 32 + lane;
        DP[warp * 128 + bitrev7(p)] = v[s];
      }
    } else {
      int j = warp - 7;
      float2 v[4];
#pragma unroll
      for (int s = 0; s < 4; s++) v[s] = Dc[(s * 32 + lane) * 7 + j];
      fft128(v, twd, lane);
#pragma unroll
      for (int s = 0; s < 4; s++) {
        int p = s * 32 + lane;
        Qc[j * 128 + bitrev7(p)] = v[s];
      }
    }
  }
  __syncthreads();

  // per-pixel output
  const float* x1 = x + (size_t)(2 * pair) * 16384;
  const float* x2 = x1 + 16384;
  uint32_t* Rh = g_Rhi + (size_t)pair * 16384;
  uint32_t* Rl = g_Rlo + (size_t)pair * 16384;
#pragma unroll 4
  for (int t = 0; t < 16; t++) {
    int idx = t * 1024 + tid;
    int m1 = idx >> 7, m2 = idx & 127;
    float K = 0.f;
#pragma unroll
    for (int dy = 0; dy < 7; dy++) {
      float2 e = cs[m1 * 7 + dy];
      K += e.x * KC[dy * 128 + m2] - e.y * KS[dy * 128 + m2];
    }
    float crx = 0.f, cry = 0.f;
#pragma unroll
    for (int j = 0; j < 7; j++) {
      float2 e = cs[m1 * 7 + j];
      float2 P = DP[j * 128 + m2];
      crx += e.x * P.x - e.y * P.y;
      cry += e.x * P.y + e.y * P.x;
    }
    float cqx = 0.f, cqy = 0.f;
#pragma unroll
    for (int j = 0; j < 7; j++) {
      float2 e = cs[m2 * 7 + j];
      float2 Q = Qc[j * 128 + m1];
      cqx += e.x * Q.x - e.y * Q.y;
      cqy += e.x * Q.y + e.y * Q.x;
    }
    float s1 = (m1 & 1) ? -1.f : 1.f;
    float s2 = (m2 & 1) ? -1.f : 1.f;
    float vx = x1[idx] * K + (s1 * crx + s2 * cqx) * 0.0078125f;
    float vy = x2[idx] * K + (s1 * cry + s2 * cqy) * 0.0078125f;
    uint32_t hi, lo;
    split2_bf16(vx, vy, hi, lo);
    Rh[idx] = hi;
    Rl[idx] = lo;
  }
}

// ---------------- weight prep: refine_w -> bf16-split packed channel pairs ----------------
__global__ void __launch_bounds__(256) wsplit_kernel(const float* __restrict__ W) {
  int idx = blockIdx.x * 256 + threadIdx.x;
  int c2 = idx & 127, o = idx >> 7;
  float xe = W[o * 256 + 2 * c2];
  float xo = W[o * 256 + 2 * c2 + 1];
  uint32_t hi, lo;
  split2_bf16(xe, xo, hi, lo);
  g_Whi[c2 * 256 + o] = hi;
  g_Wlo[c2 * 256 + o] = lo;
}

// ---------------- bf16 MMA helper ----------------
__device__ __forceinline__ void mma_bf16(float* c, uint32_t a0, uint32_t a1, uint32_t a2, uint32_t a3,
                                         uint32_t b0, uint32_t b1) {
  asm volatile(
      "mma.sync.aligned.m16n8k16.row.col.f32.bf16.bf16.f32 "
      "{%0,%1,%2,%3}, {%4,%5,%6,%7}, {%8,%9}, {%0,%1,%2,%3};"
      : "+f"(c[0]), "+f"(c[1]), "+f"(c[2]), "+f"(c[3])
      : "r"(a0), "r"(a1), "r"(a2), "r"(a3), "r"(b0), "r"(b1));
}

// ---------------- channel mix GEMM (3-term bf16, cp.async double-buffered) + bilinear epilogue ----------------
#define MIX_SA 4224   // 16*264 per stage
#define MIX_SB 1408   // 16*88  per stage
__global__ void __launch_bounds__(256, 2) mix_kernel(const float* __restrict__ xh, float* __restrict__ out) {
  extern __shared__ uint32_t smx[];
  uint32_t* AsHi = smx;
  uint32_t* AsLo = smx + 2 * MIX_SA;
  uint32_t* BsHi = smx + 4 * MIX_SA;
  uint32_t* BsLo = smx + 4 * MIX_SA + 2 * MIX_SB;

  int b = blockIdx.z;
  int h = blockIdx.x;
  int wBase = blockIdx.y * 64;
  int tid = threadIdx.x;
  int warp = tid >> 5, lane = tid & 31;
  int lr = lane >> 2, lc = lane & 3;
  int warpO = warp * 32;

  float acc[2][8][4];
#pragma unroll
  for (int mt = 0; mt < 2; mt++)
#pragma unroll
    for (int nt = 0; nt < 8; nt++)
#pragma unroll
      for (int q = 0; q < 4; q++) acc[mt][nt][q] = 0.f;

  const uint32_t* RhB = g_Rhi + (size_t)b * 128 * 16384 + h * 128 + wBase;
  const uint32_t* RlB = g_Rlo + (size_t)b * 128 * 16384 + h * 128 + wBase;

  auto load_stage = [&](int st, int kb) {
#pragma unroll
    for (int it = 0; it < 8; it++) {
      int item = it * 256 + tid;
      int o2 = item & 127;
      int k2 = item >> 7;
      cp_async8(&AsHi[st * MIX_SA + k2 * 264 + o2 * 2], &g_Whi[(kb * 16 + k2) * 256 + o2 * 2]);
      cp_async8(&AsLo[st * MIX_SA + k2 * 264 + o2 * 2], &g_Wlo[(kb * 16 + k2) * 256 + o2 * 2]);
    }
#pragma unroll
    for (int it = 0; it < 2; it++) {
      int item = it * 256 + tid;
      int w2 = item & 31;
      int k2 = item >> 5;
      cp_async8(&BsHi[st * MIX_SB + k2 * 88 + w2 * 2], &RhB[(size_t)(kb * 16 + k2) * 16384 + w2 * 2]);
      cp_async8(&BsLo[st * MIX_SB + k2 * 88 + w2 * 2], &RlB[(size_t)(kb * 16 + k2) * 16384 + w2 * 2]);
    }
    cp_commit();
  };

  load_stage(0, 0);
  for (int kb = 0; kb < 8; kb++) {
    int st = kb & 1;
    if (kb + 1 < 8) {
      load_stage(1 - st, kb + 1);
      cp_wait_group<1>();
    } else {
      cp_wait_group<0>();
    }
    __syncthreads();
    const uint32_t* aH = AsHi + st * MIX_SA;
    const uint32_t* aL = AsLo + st * MIX_SA;
    const uint32_t* bH = BsHi + st * MIX_SB;
    const uint32_t* bL = BsLo + st * MIX_SB;
#pragma unroll
    for (int s = 0; s < 2; s++) {
      uint32_t ahi[2][4], alo[2][4];
#pragma unroll
      for (int mt = 0; mt < 2; mt++) {
#pragma unroll
        for (int rg = 0; rg < 4; rg++) {
          int k2 = s * 8 + lc + 4 * (rg >> 1);
          int o = warpO + mt * 16 + lr + 8 * (rg & 1);
          ahi[mt][rg] = aH[k2 * 264 + o];
          alo[mt][rg] = aL[k2 * 264 + o];
        }
      }
      int kr0 = (s * 8 + lc) * 88 + lr;
      int kr1 = (s * 8 + lc + 4) * 88 + lr;
#pragma unroll
      for (int nt = 0; nt < 8; nt++) {
        uint32_t b0h = bH[kr0 + nt * 8];
        uint32_t b1h = bH[kr1 + nt * 8];
        uint32_t b0l = bL[kr0 + nt * 8];
        uint32_t b1l = bL[kr1 + nt * 8];
#pragma unroll
        for (int mt = 0; mt < 2; mt++) {
          mma_bf16(acc[mt][nt], ahi[mt][0], ahi[mt][1], ahi[mt][2], ahi[mt][3], b0h, b1h);
          mma_bf16(acc[mt][nt], ahi[mt][0], ahi[mt][1], ahi[mt][2], ahi[mt][3], b0l, b1l);
          mma_bf16(acc[mt][nt], alo[mt][0], alo[mt][1], alo[mt][2], alo[mt][3], b0h, b1h);
        }
      }
    }
    __syncthreads();
  }

  float hin = 0.5f * (float)h - 0.25f;
  int hi0 = hin < 0.f ? 0 : (int)hin;
  float hf = hin < 0.f ? 0.f : hin - (float)hi0;
  int hi1 = hi0 + 1 < 64 ? hi0 + 1 : 63;

#pragma unroll
  for (int mt = 0; mt < 2; mt++) {
#pragma unroll
    for (int half = 0; half < 2; half++) {
      int o = warpO + mt * 16 + lr + 8 * half;
      const float* xb = xh + (size_t)(b * 256 + o) * 4096;
      const float* r0 = xb + hi0 * 64;
      const float* r1 = xb + hi1 * 64;
      float* orow = out + (size_t)(b * 256 + o) * 16384 + h * 128;
#pragma unroll
      for (int nt = 0; nt < 8; nt++) {
        int w0 = wBase + nt * 8 + 2 * lc;
        float v[2];
#pragma unroll
        for (int j = 0; j < 2; j++) {
          int w = w0 + j;
          float win = 0.5f * (float)w - 0.25f;
          int wi0 = win < 0.f ? 0 : (int)win;
          float wf = win < 0.f ? 0.f : win - (float)wi0;
          int wi1 = wi0 + 1 < 64 ? wi0 + 1 : 63;
          float top = r0[wi0] * (1.f - wf) + r0[wi1] * wf;
          float bot = r1[wi0] * (1.f - wf) + r1[wi1] * wf;
          v[j] = acc[mt][nt][half * 2 + j] + top * (1.f - hf) + bot * hf;
        }
        *(float2*)&orow[w0] = make_float2(v[0], v[1]);
      }
    }
  }
}

// ---------------- launch ----------------
extern "C" void kernel_launch(void* const* d_in, const int* in_sizes, int n_in,
                              void* d_out, int out_size) {
  const float* x_high = (const float*)d_in[0];
  const float* x_low = (const float*)d_in[1];
  const float* w1 = (const float*)d_in[2];
  const float* b1 = (const float*)d_in[3];
  const float* w2 = (const float*)d_in[4];
  const float* b2 = (const float*)d_in[5];
  const float* refine_w = (const float*)d_in[6];
  float* out = (float*)d_out;

  const int SMEM_FFT = 2 * 128 * 129 * 4;                    // 132096 B
  const int SMEM_FIN = 6912 * 8 + 2 * 896 * 4;               // 55296 + 7168 = 62464 B
  const int SMEM_MIX = (4 * MIX_SA + 4 * MIX_SB) * 4;        // 90112 B
  cudaFuncSetAttribute((const void*)fwd_fft_pair_kernel, cudaFuncAttributeMaxDynamicSharedMemorySize, SMEM_FFT);
  cudaFuncSetAttribute((const void*)final_kernel, cudaFuncAttributeMaxDynamicSharedMemorySize, SMEM_FIN);
  cudaFuncSetAttribute((const void*)mix_kernel, cudaFuncAttributeMaxDynamicSharedMemorySize, SMEM_MIX);

  wsplit_kernel<<<128, 256>>>(refine_w);
  fwd_fft_pair_kernel<<<1024, 1024, SMEM_FFT>>>(x_low);
  mlp_kernel<<<8, 256>>>(w1, b1, w2, b2);
  final_kernel<<<1024, 1024, SMEM_FIN>>>(x_low);
  mix_kernel<<<dim3(128, 2, 8), 256, SMEM_MIX>>>(x_high, out);
}